// round 11
// baseline (speedup 1.0000x reference)
#include <cuda_runtime.h>
#include <cuda_bf16.h>
#include <math.h>
#include <stdint.h>

#define NTOK 175616   // 56*56*56
#define CDIM 96
#define NW   512
#define WN   343
#define HIDD 384

typedef unsigned long long u64;
typedef unsigned int u32;
union F4U { float4 f; ulonglong2 u; };

__device__ __forceinline__ u64 ffma2(u64 a, u64 b, u64 c) {
    u64 d; asm("fma.rn.f32x2 %0, %1, %2, %3;" : "=l"(d) : "l"(a), "l"(b), "l"(c));
    return d;
}
__device__ __forceinline__ void bsplit(float v, __nv_bfloat16& h, __nv_bfloat16& l) {
    h = __float2bfloat16_rn(v);
    l = __float2bfloat16_rn(v - __bfloat162float(h));
}
__device__ __forceinline__ u32 pack_bf(__nv_bfloat16 a, __nv_bfloat16 b) {
    return (u32)__bfloat16_as_ushort(a) | ((u32)__bfloat16_as_ushort(b) << 16);
}
__device__ __forceinline__ float gelu_f(float v) {
    return 0.5f * v * (1.f + erff(v * 0.70710678118654752f));
}
__device__ __forceinline__ void mma16816(float* d, const u32* a, u32 b0, u32 b1) {
    asm volatile("mma.sync.aligned.m16n8k16.row.col.f32.bf16.bf16.f32 "
                 "{%0,%1,%2,%3}, {%4,%5,%6,%7}, {%8,%9}, {%0,%1,%2,%3};"
                 : "+f"(d[0]), "+f"(d[1]), "+f"(d[2]), "+f"(d[3])
                 : "r"(a[0]), "r"(a[1]), "r"(a[2]), "r"(a[3]), "r"(b0), "r"(b1));
}
__device__ __forceinline__ void ldmx4(u32* r, const __nv_bfloat16* p) {
    u32 addr = (u32)__cvta_generic_to_shared(p);
    asm volatile("ldmatrix.sync.aligned.m8n8.x4.shared.b16 {%0,%1,%2,%3}, [%4];"
                 : "=r"(r[0]), "=r"(r[1]), "=r"(r[2]), "=r"(r[3]) : "r"(addr));
}
__device__ __forceinline__ void ldmx4t(u32* r, const __nv_bfloat16* p) {
    u32 addr = (u32)__cvta_generic_to_shared(p);
    asm volatile("ldmatrix.sync.aligned.m8n8.x4.trans.shared.b16 {%0,%1,%2,%3}, [%4];"
                 : "=r"(r[0]), "=r"(r[1]), "=r"(r[2]), "=r"(r[3]) : "r"(addr));
}

// -------------------- scratch (device globals) -------------------------------
__device__ __nv_bfloat16 g_xwh[(size_t)NTOK*CDIM], g_xwl[(size_t)NTOK*CDIM];
__device__ float g_qp [(size_t)NTOK*CDIM];
__device__ float g_kp [(size_t)NTOK*CDIM];
__device__ float g_vp [(size_t)NTOK*CDIM];
__device__ __nv_bfloat16 g_qh[(size_t)NTOK*CDIM], g_ql[(size_t)NTOK*CDIM];
__device__ __nv_bfloat16 g_kh[(size_t)NTOK*CDIM], g_kl[(size_t)NTOK*CDIM];
__device__ __nv_bfloat16 g_vh[(size_t)NTOK*CDIM], g_vl[(size_t)NTOK*CDIM];
__device__ float g_ot [(size_t)NTOK*CDIM];   // attention out, axis-mixed: flat = c*343 + n
__device__ float g_xres[(size_t)NTOK*CDIM];
__device__ __nv_bfloat16 g_l2h[(size_t)NTOK*CDIM], g_l2l[(size_t)NTOK*CDIM];
__device__ __nv_bfloat16 g_hh[(size_t)NTOK*HIDD], g_hl[(size_t)NTOK*HIDD];
__device__ __nv_bfloat16 g_wqh[288*96], g_wql[288*96];
__device__ __nv_bfloat16 g_f1h[HIDD*96], g_f1l[HIDD*96];
__device__ __nv_bfloat16 g_f2h[96*HIDD], g_f2l[96*HIDD];
__device__ float g_bqkv[288];

// -------------------- weight prep --------------------------------------------
__global__ void k_prep1(const float* __restrict__ wq, const float* __restrict__ bq,
                        const float* __restrict__ wk, const float* __restrict__ bk,
                        const float* __restrict__ wv, const float* __restrict__ bv) {
    int i = blockIdx.x * 256 + threadIdx.x;
    if (i < 3*96*96) {
        int t = i / 9216, r = i % 9216;
        float v = (t == 0) ? wq[r] : (t == 1) ? wk[r] : wv[r];
        bsplit(v, g_wqh[i], g_wql[i]);
    }
    if (i < 288) {
        int t = i / 96, r = i % 96;
        g_bqkv[i] = (t == 0) ? bq[r] : (t == 1) ? bk[r] : bv[r];
    }
}
__global__ void k_prep2(const float* __restrict__ f1w, const float* __restrict__ f2w) {
    int i = blockIdx.x * 256 + threadIdx.x;
    if (i < HIDD*96) {
        bsplit(f1w[i], g_f1h[i], g_f1l[i]);
        bsplit(f2w[i], g_f2h[i], g_f2l[i]);
    }
}

// -------------------- LN1 + roll(-3) + window partition -----------------------
__global__ __launch_bounds__(256)
void k_ln1(const float* __restrict__ x,
           const float* __restrict__ gg, const float* __restrict__ bb) {
    __shared__ float xs[64*101];
    int p0 = blockIdx.x * 64;
    int tid = threadIdx.x, lane = tid & 31, wp = tid >> 5;
    for (int e = tid; e < 96*64; e += 256) {
        int c = e >> 6, i = e & 63;
        xs[i*101 + c] = x[(size_t)c*NTOK + p0 + i];
    }
    __syncthreads();
    #pragma unroll
    for (int ii = wp; ii < 64; ii += 8) {
        int p = p0 + ii;
        int s = p / 3136, r = p % 3136, h = r / 56, w = r % 56;
        int s2 = (s >= 3) ? s - 3 : s + 53;
        int h2 = (h >= 3) ? h - 3 : h + 53;
        int w2 = (w >= 3) ? w - 3 : w + 53;
        int win = (s2/7)*64 + (h2/7)*8 + (w2/7);
        int t   = (s2%7)*49 + (h2%7)*7 + (w2%7);
        float v0 = xs[ii*101 + lane];
        float v1 = xs[ii*101 + lane + 32];
        float v2 = xs[ii*101 + lane + 64];
        float sum = v0 + v1 + v2, sq = v0*v0 + v1*v1 + v2*v2;
        #pragma unroll
        for (int o = 16; o; o >>= 1) {
            sum += __shfl_xor_sync(0xffffffffu, sum, o);
            sq  += __shfl_xor_sync(0xffffffffu, sq, o);
        }
        float mean = sum * (1.f/96.f);
        float var  = sq * (1.f/96.f) - mean*mean;
        float inv  = rsqrtf(var + 1e-5f);
        size_t ob = ((size_t)win*WN + t)*CDIM;
        float y0 = (v0 - mean)*inv*gg[lane]      + bb[lane];
        float y1 = (v1 - mean)*inv*gg[lane + 32] + bb[lane + 32];
        float y2 = (v2 - mean)*inv*gg[lane + 64] + bb[lane + 64];
        bsplit(y0, g_xwh[ob + lane],      g_xwl[ob + lane]);
        bsplit(y1, g_xwh[ob + lane + 32], g_xwl[ob + lane + 32]);
        bsplit(y2, g_xwh[ob + lane + 64], g_xwl[ob + lane + 64]);
    }
}

// -------------------- tensor-core GEMM (bf16 split, mma.sync + ldmatrix) -----
// EPI 0: qkv (K=96, 3 N-slices, A loaded once). EPI 1: MLP1 GELU (K=96, 4 slices).
// EPI 2: MLP2 (K=384 chunked, 1 slice, residual + transposed store).
#define SA_STRIDE 104
#define TG_A_HI 0
#define TG_A_LO (128*104)          // bf16 units
#define TG_B_HI (2*128*104)
#define TG_B_LO (2*128*104 + 96*104)
#define TG_SMEM ((2*128*104 + 2*96*104) * 2)   // 93184 bytes

template<int EPI>
__global__ __launch_bounds__(256, 2)
void k_tgemm(const __nv_bfloat16* __restrict__ Ah, const __nv_bfloat16* __restrict__ Al,
             const __nv_bfloat16* __restrict__ Wh, const __nv_bfloat16* __restrict__ Wl,
             const float* __restrict__ bias, int K,
             float* __restrict__ O0, float* __restrict__ O1, float* __restrict__ O2,
             __nv_bfloat16* __restrict__ Oh, __nv_bfloat16* __restrict__ Ol,
             const float* __restrict__ Res, float* __restrict__ OutT) {
    extern __shared__ char smemc[];
    __nv_bfloat16* sA = (__nv_bfloat16*)smemc;
    int tid = threadIdx.x, lane = tid & 31, wid = tid >> 5;
    int g = lane >> 2, tg = lane & 3;
    int bm = blockIdx.x * 128;
    int warpM = (wid & 3) * 32, warpN = (wid >> 2) * 48;
    int lr = lane & 15;
    int lc = (lane & 16) ? 8 : 0;

    if (EPI == 2) {
        float acc[2][6][4];
        #pragma unroll
        for (int mt = 0; mt < 2; mt++)
            #pragma unroll
            for (int nt = 0; nt < 6; nt++)
                #pragma unroll
                for (int i = 0; i < 4; i++) acc[mt][nt][i] = 0.f;

        int nch = K / 96;
        for (int kc = 0; kc < nch; kc++) {
            const __nv_bfloat16* pAh = Ah + (size_t)bm*K + kc*96;
            const __nv_bfloat16* pAl = Al + (size_t)bm*K + kc*96;
            for (int e = tid; e < 128*24; e += 256) {
                int r = e / 24, c4 = e % 24;
                *(uint2*)(sA + TG_A_HI + r*SA_STRIDE + c4*4) = *(const uint2*)(pAh + (size_t)r*K + c4*4);
                *(uint2*)(sA + TG_A_LO + r*SA_STRIDE + c4*4) = *(const uint2*)(pAl + (size_t)r*K + c4*4);
            }
            const __nv_bfloat16* pWh = Wh + kc*96;
            const __nv_bfloat16* pWl = Wl + kc*96;
            for (int e = tid; e < 96*24; e += 256) {
                int r = e / 24, c4 = e % 24;
                *(uint2*)(sA + TG_B_HI + r*SA_STRIDE + c4*4) = *(const uint2*)(pWh + (size_t)r*K + c4*4);
                *(uint2*)(sA + TG_B_LO + r*SA_STRIDE + c4*4) = *(const uint2*)(pWl + (size_t)r*K + c4*4);
            }
            __syncthreads();
            #pragma unroll
            for (int ks = 0; ks < 6; ks++) {
                int k0 = ks * 16;
                u32 ah[2][4], al_[2][4];
                #pragma unroll
                for (int mt = 0; mt < 2; mt++) {
                    int ro = (warpM + mt*16 + lr)*SA_STRIDE + k0 + lc;
                    ldmx4(ah[mt],  sA + TG_A_HI + ro);
                    ldmx4(al_[mt], sA + TG_A_LO + ro);
                }
                u32 bh[3][4], bl[3][4];
                #pragma unroll
                for (int np = 0; np < 3; np++) {
                    int ro = (warpN + np*16 + lr)*SA_STRIDE + k0 + lc;
                    ldmx4(bh[np], sA + TG_B_HI + ro);
                    ldmx4(bl[np], sA + TG_B_LO + ro);
                }
                #pragma unroll
                for (int np = 0; np < 3; np++) {
                    #pragma unroll
                    for (int mt = 0; mt < 2; mt++) {
                        mma16816(acc[mt][2*np],   ah[mt],  bh[np][0], bh[np][2]);
                        mma16816(acc[mt][2*np+1], ah[mt],  bh[np][1], bh[np][3]);
                        mma16816(acc[mt][2*np],   ah[mt],  bl[np][0], bl[np][2]);
                        mma16816(acc[mt][2*np+1], ah[mt],  bl[np][1], bl[np][3]);
                        mma16816(acc[mt][2*np],   al_[mt], bh[np][0], bh[np][2]);
                        mma16816(acc[mt][2*np+1], al_[mt], bh[np][1], bh[np][3]);
                    }
                }
            }
            __syncthreads();
        }
        // residual + transposed store
        float* st = (float*)smemc;    // 96 cols x 132 rows
        #pragma unroll
        for (int mt = 0; mt < 2; mt++) {
            int rl = warpM + mt*16 + g;
            #pragma unroll
            for (int nt = 0; nt < 6; nt++) {
                int c = warpN + nt*8 + 2*tg;
                float b0 = bias[c], b1 = bias[c + 1];
                #pragma unroll
                for (int hrow = 0; hrow < 2; hrow++) {
                    int row = rl + hrow*8;
                    const float* rr = Res + (size_t)(bm + row)*96;
                    st[(c)  *132 + row] = acc[mt][nt][2*hrow]   + b0 + rr[c];
                    st[(c+1)*132 + row] = acc[mt][nt][2*hrow+1] + b1 + rr[c+1];
                }
            }
        }
        __syncthreads();
        for (int e = tid; e < 96*128; e += 256) {
            int col = e >> 7, r = e & 127;
            OutT[(size_t)col*NTOK + bm + r] = st[col*132 + r];
        }
        return;
    }

    // ---- EPI 0 / 1: K = 96, A loaded once, loop over N-slices ----
    {
        const __nv_bfloat16* pAh = Ah + (size_t)bm*96;
        const __nv_bfloat16* pAl = Al + (size_t)bm*96;
        for (int e = tid; e < 128*24; e += 256) {
            int r = e / 24, c4 = e % 24;
            *(uint2*)(sA + TG_A_HI + r*SA_STRIDE + c4*4) = *(const uint2*)(pAh + (size_t)r*96 + c4*4);
            *(uint2*)(sA + TG_A_LO + r*SA_STRIDE + c4*4) = *(const uint2*)(pAl + (size_t)r*96 + c4*4);
        }
        const int NY = (EPI == 0) ? 3 : 4;
        for (int ys = 0; ys < NY; ys++) {
            int bn = ys * 96;
            __syncthreads();     // orders A stores (ys=0) / prior B reads (ys>0)
            const __nv_bfloat16* pWh = Wh + (size_t)bn*96;
            const __nv_bfloat16* pWl = Wl + (size_t)bn*96;
            for (int e = tid; e < 96*24; e += 256) {
                int r = e / 24, c4 = e % 24;
                *(uint2*)(sA + TG_B_HI + r*SA_STRIDE + c4*4) = *(const uint2*)(pWh + (size_t)r*96 + c4*4);
                *(uint2*)(sA + TG_B_LO + r*SA_STRIDE + c4*4) = *(const uint2*)(pWl + (size_t)r*96 + c4*4);
            }
            __syncthreads();

            float acc[2][6][4];
            #pragma unroll
            for (int mt = 0; mt < 2; mt++)
                #pragma unroll
                for (int nt = 0; nt < 6; nt++)
                    #pragma unroll
                    for (int i = 0; i < 4; i++) acc[mt][nt][i] = 0.f;

            #pragma unroll
            for (int ks = 0; ks < 6; ks++) {
                int k0 = ks * 16;
                u32 ah[2][4], al_[2][4];
                #pragma unroll
                for (int mt = 0; mt < 2; mt++) {
                    int ro = (warpM + mt*16 + lr)*SA_STRIDE + k0 + lc;
                    ldmx4(ah[mt],  sA + TG_A_HI + ro);
                    ldmx4(al_[mt], sA + TG_A_LO + ro);
                }
                u32 bh[3][4], bl[3][4];
                #pragma unroll
                for (int np = 0; np < 3; np++) {
                    int ro = (warpN + np*16 + lr)*SA_STRIDE + k0 + lc;
                    ldmx4(bh[np], sA + TG_B_HI + ro);
                    ldmx4(bl[np], sA + TG_B_LO + ro);
                }
                #pragma unroll
                for (int np = 0; np < 3; np++) {
                    #pragma unroll
                    for (int mt = 0; mt < 2; mt++) {
                        mma16816(acc[mt][2*np],   ah[mt],  bh[np][0], bh[np][2]);
                        mma16816(acc[mt][2*np+1], ah[mt],  bh[np][1], bh[np][3]);
                        mma16816(acc[mt][2*np],   ah[mt],  bl[np][0], bl[np][2]);
                        mma16816(acc[mt][2*np+1], ah[mt],  bl[np][1], bl[np][3]);
                        mma16816(acc[mt][2*np],   al_[mt], bh[np][0], bh[np][2]);
                        mma16816(acc[mt][2*np+1], al_[mt], bh[np][1], bh[np][3]);
                    }
                }
            }

            if (EPI == 0) {
                float* O = (ys == 0) ? O0 : (ys == 1) ? O1 : O2;
                #pragma unroll
                for (int mt = 0; mt < 2; mt++) {
                    int r0 = bm + warpM + mt*16 + g;
                    #pragma unroll
                    for (int nt = 0; nt < 6; nt++) {
                        int c = warpN + nt*8 + 2*tg;
                        float b0 = bias[bn + c], b1 = bias[bn + c + 1];
                        *(float2*)(O + (size_t)r0*96 + c)       = make_float2(acc[mt][nt][0] + b0, acc[mt][nt][1] + b1);
                        *(float2*)(O + (size_t)(r0 + 8)*96 + c) = make_float2(acc[mt][nt][2] + b0, acc[mt][nt][3] + b1);
                    }
                }
            } else {
                #pragma unroll
                for (int mt = 0; mt < 2; mt++) {
                    int r0 = bm + warpM + mt*16 + g;
                    #pragma unroll
                    for (int nt = 0; nt < 6; nt++) {
                        int c = warpN + nt*8 + 2*tg;
                        float b0 = bias[bn + c], b1 = bias[bn + c + 1];
                        #pragma unroll
                        for (int hrow = 0; hrow < 2; hrow++) {
                            int row = r0 + hrow*8;
                            float v0 = gelu_f(acc[mt][nt][2*hrow]   + b0);
                            float v1 = gelu_f(acc[mt][nt][2*hrow+1] + b1);
                            __nv_bfloat16 h0, l0, h1, l1;
                            bsplit(v0, h0, l0);
                            bsplit(v1, h1, l1);
                            *(u32*)(Oh + (size_t)row*HIDD + bn + c) = pack_bf(h0, h1);
                            *(u32*)(Ol + (size_t)row*HIDD + bn + c) = pack_bf(l0, l1);
                        }
                    }
                }
            }
        }
    }
}

// -------------------- depthwise 3x3x3 (fused q/k/v, bf16-split output) --------
__global__ __launch_bounds__(392, 2)
void k_dw(const float* __restrict__ In0, const float* __restrict__ In1, const float* __restrict__ In2,
          const float* __restrict__ W0, const float* __restrict__ W1, const float* __restrict__ W2,
          const float* __restrict__ B0, const float* __restrict__ B1, const float* __restrict__ B2,
          __nv_bfloat16* __restrict__ OH0, __nv_bfloat16* __restrict__ OH1, __nv_bfloat16* __restrict__ OH2,
          __nv_bfloat16* __restrict__ OL0, __nv_bfloat16* __restrict__ OL1, __nv_bfloat16* __restrict__ OL2) {
    __shared__ float sin_[WN*32];
    __shared__ float wsm[27*32];
    int z = blockIdx.z;
    const float* In = (z == 0) ? In0 : (z == 1) ? In1 : In2;
    const float* Wt = (z == 0) ? W0  : (z == 1) ? W1  : W2;
    const float* Bi = (z == 0) ? B0  : (z == 1) ? B1  : B2;
    __nv_bfloat16* OutH = (z == 0) ? OH0 : (z == 1) ? OH1 : OH2;
    __nv_bfloat16* OutL = (z == 0) ? OL0 : (z == 1) ? OL1 : OL2;

    int win = blockIdx.x;
    int c0 = blockIdx.y * 32;
    int tid = threadIdx.x;
    const float* inw = In + (size_t)win*WN*CDIM + c0;
    for (int e = tid; e < WN*8; e += 392) {
        int t = e >> 3, c4 = e & 7;
        *(float4*)(sin_ + t*32 + c4*4) = *(const float4*)(inw + t*96 + c4*4);
    }
    for (int e = tid; e < 27*32; e += 392) {
        int k = e >> 5, cc = e & 31;
        wsm[k*32 + cc] = Wt[(c0 + cc)*27 + k];
    }
    __syncthreads();

    int g = tid & 7, dy = (tid >> 3) % 7, dz = tid / 56;
    int cc = g * 4;
    F4U bias4; bias4.f = *(const float4*)(Bi + c0 + cc);
    u64 ax[7], ay[7];
    #pragma unroll
    for (int x = 0; x < 7; x++) { ax[x] = bias4.u.x; ay[x] = bias4.u.y; }

    #pragma unroll
    for (int kd = 0; kd < 3; kd++) {
        int nz = dz + kd - 1;
        if ((unsigned)nz >= 7u) continue;
        #pragma unroll
        for (int kh = 0; kh < 3; kh++) {
            int ny = dy + kh - 1;
            if ((unsigned)ny >= 7u) continue;
            const float* row = sin_ + (nz*49 + ny*7)*32 + cc;
            F4U iv[7];
            #pragma unroll
            for (int x = 0; x < 7; x++) iv[x].f = *(const float4*)(row + x*32);
            const float* wp_ = wsm + (kd*9 + kh*3)*32 + cc;
            F4U w0, w1, w2;
            w0.f = *(const float4*)(wp_);
            w1.f = *(const float4*)(wp_ + 32);
            w2.f = *(const float4*)(wp_ + 64);
            #pragma unroll
            for (int x = 1; x < 7; x++) {
                ax[x] = ffma2(w0.u.x, iv[x-1].u.x, ax[x]);
                ay[x] = ffma2(w0.u.y, iv[x-1].u.y, ay[x]);
            }
            #pragma unroll
            for (int x = 0; x < 7; x++) {
                ax[x] = ffma2(w1.u.x, iv[x].u.x, ax[x]);
                ay[x] = ffma2(w1.u.y, iv[x].u.y, ay[x]);
            }
            #pragma unroll
            for (int x = 0; x < 6; x++) {
                ax[x] = ffma2(w2.u.x, iv[x+1].u.x, ax[x]);
                ay[x] = ffma2(w2.u.y, iv[x+1].u.y, ay[x]);
            }
        }
    }

    size_t ob = (size_t)win*WN*CDIM + (size_t)(dz*49 + dy*7)*96 + c0 + cc;
    #pragma unroll
    for (int x = 0; x < 7; x++) {
        F4U o; o.u.x = ax[x]; o.u.y = ay[x];
        __nv_bfloat16 h0,l0,h1,l1,h2,l2,h3,l3;
        bsplit(o.f.x, h0, l0); bsplit(o.f.y, h1, l1);
        bsplit(o.f.z, h2, l2); bsplit(o.f.w, h3, l3);
        uint2 vh = make_uint2(pack_bf(h0,h1), pack_bf(h2,h3));
        uint2 vl = make_uint2(pack_bf(l0,l1), pack_bf(l2,l3));
        *(uint2*)(OutH + ob + (size_t)x*96) = vh;
        *(uint2*)(OutL + ob + (size_t)x*96) = vl;
    }
}

// -------------------- tensor-core fused attention (S in registers) ------------
// 256 thr = 8 warps in 4(rows of 16) x 2(cols of 176) grid. q-chunks of 64.
#define AB_KH 0
#define AB_KL 73216
#define AB_QH 146432
#define AB_QL 159744
#define AB_RED 173056
#define AB_OPART 146432
#define AT_SMEM 174080

__global__ __launch_bounds__(256, 1)
void k_attn(const __nv_bfloat16* __restrict__ Qh, const __nv_bfloat16* __restrict__ Ql,
            const __nv_bfloat16* __restrict__ Kh, const __nv_bfloat16* __restrict__ Kl,
            const __nv_bfloat16* __restrict__ Vh, const __nv_bfloat16* __restrict__ Vl) {
    extern __shared__ char smb[];
    __nv_bfloat16* kh_s = (__nv_bfloat16*)(smb + AB_KH);
    __nv_bfloat16* kl_s = (__nv_bfloat16*)(smb + AB_KL);
    __nv_bfloat16* qh_s = (__nv_bfloat16*)(smb + AB_QH);
    __nv_bfloat16* ql_s = (__nv_bfloat16*)(smb + AB_QL);
    float* redmax = (float*)(smb + AB_RED);          // [64][2]
    float* redsum = (float*)(smb + AB_RED) + 128;    // [64][2]
    float* opart  = (float*)(smb + AB_OPART);        // [64][96]
    float* ostg   = (float*)smb;                     // [96][66]

    int win = blockIdx.x;
    int tid = threadIdx.x, lane = tid & 31, wp = tid >> 5;
    int g = lane >> 2, tg = lane & 3;
    int lr = lane & 15, lc = (lane & 16) ? 8 : 0;
    int wm = wp & 3, wn = wp >> 2;      // 4 x 2 warp grid

    const __nv_bfloat16* gqh = Qh + (size_t)win*WN*CDIM;
    const __nv_bfloat16* gql = Ql + (size_t)win*WN*CDIM;
    const __nv_bfloat16* gkh = Kh + (size_t)win*WN*CDIM;
    const __nv_bfloat16* gkl = Kl + (size_t)win*WN*CDIM;
    const __nv_bfloat16* gvh = Vh + (size_t)win*WN*CDIM;
    const __nv_bfloat16* gvl = Vl + (size_t)win*WN*CDIM;
    float* ob = g_ot + (size_t)win*WN*CDIM;

    int ws = win >> 6, hs = (win >> 3) & 7, wd = win & 7;
    bool bz = (ws == 7), bh_ = (hs == 7), bw = (wd == 7);
    const float scale = 0.10206207261596575f;   // 1/sqrt(96)

    // mask bits for this thread's 44 S-positions (idx = 2*ct + e, ct 0..21)
    u64 mzm = 0, mhm = 0, mwm = 0, mvm = 0;
    #pragma unroll
    for (int idx = 0; idx < 44; idx++) {
        int m = wn*176 + (idx >> 1)*8 + 2*tg + (idx & 1);
        if (m < WN) {
            int dzm = m / 49, rm = m % 49, dym = rm / 7, dxm = rm % 7;
            if (dzm < 4) mzm |= 1ull << idx;
            if (dym < 4) mhm |= 1ull << idx;
            if (dxm < 4) mwm |= 1ull << idx;
            mvm |= 1ull << idx;
        }
    }

    for (int chunk = 0; chunk < 6; chunk++) {
        int qbase = chunk * 64;
        __syncthreads();   // prev chunk's O stores / V reads done
        for (int e = tid; e < 343*24; e += 256) {
            int r = e / 24, c4 = e % 24;
            *(uint2*)(kh_s + r*104 + c4*4) = *(const uint2*)(gkh + (size_t)r*96 + c4*4);
            *(uint2*)(kl_s + r*104 + c4*4) = *(const uint2*)(gkl + (size_t)r*96 + c4*4);
        }
        for (int e = tid; e < 64*24; e += 256) {
            int r = e / 24, c4 = e % 24;
            int q = qbase + r;
            uint2 vh = make_uint2(0u, 0u), vl = make_uint2(0u, 0u);
            if (q < WN) {
                vh = *(const uint2*)(gqh + (size_t)q*96 + c4*4);
                vl = *(const uint2*)(gql + (size_t)q*96 + c4*4);
            }
            *(uint2*)(qh_s + r*104 + c4*4) = vh;
            *(uint2*)(ql_s + r*104 + c4*4) = vl;
        }
        __syncthreads();

        // ---- phase S: sacc[22][4] = Q Kt (rows wm*16.., cols wn*176..) ----
        float sacc[22][4];
        #pragma unroll
        for (int ct = 0; ct < 22; ct++)
            #pragma unroll
            for (int i = 0; i < 4; i++) sacc[ct][i] = 0.f;

        #pragma unroll
        for (int ks = 0; ks < 6; ks++) {
            int k0 = ks * 16;
            u32 aqh[4], aql[4];
            int ro = (wm*16 + lr)*104 + k0 + lc;
            ldmx4(aqh, qh_s + ro);
            ldmx4(aql, ql_s + ro);
            #pragma unroll
            for (int bg = 0; bg < 11; bg++) {
                u32 bh[4], bl[4];
                int rk = (wn*176 + bg*16 + lr)*104 + k0 + lc;
                ldmx4(bh, kh_s + rk);
                ldmx4(bl, kl_s + rk);
                mma16816(sacc[2*bg],   aqh, bh[0], bh[2]);
                mma16816(sacc[2*bg],   aqh, bl[0], bl[2]);
                mma16816(sacc[2*bg],   aql, bh[0], bh[2]);
                mma16816(sacc[2*bg+1], aqh, bh[1], bh[3]);
                mma16816(sacc[2*bg+1], aqh, bl[1], bl[3]);
                mma16816(sacc[2*bg+1], aql, bh[1], bh[3]);
            }
        }

        // ---- mask + scale + row max (in registers) ----
        bool qv[2]; bool gz[2], gh[2], gw[2];
        #pragma unroll
        for (int h = 0; h < 2; h++) {
            int q = qbase + wm*16 + g + 8*h;
            qv[h] = q < WN;
            int dzq = q / 49, rq = q % 49, dyq = rq / 7, dxq = rq % 7;
            gz[h] = dzq < 4; gh[h] = dyq < 4; gw[h] = dxq < 4;
        }
        float mxh[2] = {-1e30f, -1e30f};
        #pragma unroll
        for (int ct = 0; ct < 22; ct++) {
            #pragma unroll
            for (int i = 0; i < 4; i++) {
                int h = i >> 1, e_ = i & 1;
                int idx = 2*ct + e_;
                float v;
                if (qv[h] && ((mvm >> idx) & 1ull)) {
                    bool same = (!bz  || ((int)gz[h] == (int)((mzm >> idx) & 1ull))) &&
                                (!bh_ || ((int)gh[h] == (int)((mhm >> idx) & 1ull))) &&
                                (!bw  || ((int)gw[h] == (int)((mwm >> idx) & 1ull)));
                    v = sacc[ct][i] * scale + (same ? 0.f : -100.f);
                } else v = -1e30f;
                sacc[ct][i] = v;
                mxh[h] = fmaxf(mxh[h], v);
            }
        }
        #pragma unroll
        for (int o = 1; o <= 2; o <<= 1) {
            mxh[0] = fmaxf(mxh[0], __shfl_xor_sync(0xffffffffu, mxh[0], o));
            mxh[1] = fmaxf(mxh[1], __shfl_xor_sync(0xffffffffu, mxh[1], o));
        }
        if (tg == 0) {
            redmax[(wm*16 + g)*2 + wn]     = mxh[0];
            redmax[(wm*16 + g + 8)*2 + wn] = mxh[1];
        }
        __syncthreads();   // also: all S-mma done -> K region dead
        float gmx[2];
        gmx[0] = fmaxf(redmax[(wm*16 + g)*2],     redmax[(wm*16 + g)*2 + 1]);
        gmx[1] = fmaxf(redmax[(wm*16 + g + 8)*2], redmax[(wm*16 + g + 8)*2 + 1]);

        // ---- exp + row sum ----
        float sh[2] = {0.f, 0.f};
        #pragma unroll
        for (int ct = 0; ct < 22; ct++) {
            #pragma unroll
            for (int i = 0; i < 4; i++) {
                int h = i >> 1;
                float e = __expf(sacc[ct][i] - gmx[h]);
                sacc[ct][i] = e;
                sh[h] += e;
            }
        }
        #pragma unroll
        for (int o = 1; o <= 2; o <<= 1) {
            sh[0] += __shfl_xor_sync(0xffffffffu, sh[0], o);
            sh[1] += __shfl_xor_sync(0xffffffffu, sh[1], o);
        }
        if (tg == 0) {
            redsum[(wm*16 + g)*2 + wn]     = sh[0];
            redsum[(wm*16 + g + 8)*2 + wn] = sh[1];
        }
        // ---- load V into dead K region (352 rows incl. zero pad) ----
        for (int e = tid; e < 352*24; e += 256) {
            int r = e / 24, c4 = e % 24;
            uint2 vh = make_uint2(0u, 0u), vl = make_uint2(0u, 0u);
            if (r < WN) {
                vh = *(const uint2*)(gvh + (size_t)r*96 + c4*4);
                vl = *(const uint2*)(gvl + (size_t)r*96 + c4*4);
            }
            *(uint2*)(kh_s + r*104 + c4*4) = vh;
            *(uint2*)(kl_s + r*104 + c4*4) = vl;
        }
        __syncthreads();
        float rinv[2];
        rinv[0] = 1.f / (redsum[(wm*16 + g)*2]     + redsum[(wm*16 + g)*2 + 1]);
        rinv[1] = 1.f / (redsum[(wm*16 + g + 8)*2] + redsum[(wm*16 + g + 8)*2 + 1]);

        // ---- phase PV: P (from regs, split on the fly) @ V ----
        float oacc[12][4];
        #pragma unroll
        for (int ct = 0; ct < 12; ct++)
            #pragma unroll
            for (int i = 0; i < 4; i++) oacc[ct][i] = 0.f;

        #pragma unroll
        for (int kt = 0; kt < 11; kt++) {
            int kv = wn*176 + kt*16;
            u32 aPh[4], aPl[4];
            {
                int c0 = 2*kt, c1 = 2*kt + 1;
                float p0 = sacc[c0][0]*rinv[0], p1 = sacc[c0][1]*rinv[0];
                float p2 = sacc[c0][2]*rinv[1], p3 = sacc[c0][3]*rinv[1];
                float p4 = sacc[c1][0]*rinv[0], p5 = sacc[c1][1]*rinv[0];
                float p6 = sacc[c1][2]*rinv[1], p7 = sacc[c1][3]*rinv[1];
                __nv_bfloat16 h0,l0,h1,l1;
                bsplit(p0,h0,l0); bsplit(p1,h1,l1);
                aPh[0] = pack_bf(h0,h1); aPl[0] = pack_bf(l0,l1);
                bsplit(p2,h0,l0); bsplit(p3,h1,l1);
                aPh[1] = pack_bf(h0,h1); aPl[1] = pack_bf(l0,l1);
                bsplit(p4,h0,l0); bsplit(p5,h1,l1);
                aPh[2] = pack_bf(h0,h1); aPl[2] = pack_bf(l0,l1);
                bsplit(p6,h0,l0); bsplit(p7,h1,l1);
                aPh[3] = pack_bf(h0,h1); aPl[3] = pack_bf(l0,l1);
            }
            #pragma unroll
            for (int nt6 = 0; nt6 < 6; nt6++) {
                u32 bvh[4], bvl[4];
                int ro = (kv + lr)*104 + nt6*16 + lc;
                ldmx4t(bvh, kh_s + ro);
                ldmx4t(bvl, kl_s + ro);
                mma16816(oacc[2*nt6],   aPh, bvh[0], bvh[1]);
                mma16816(oacc[2*nt6],   aPh, bvl[0], bvl[1]);
                mma16816(oacc[2*nt6],   aPl, bvh[0], bvh[1]);
                mma16816(oacc[2*nt6+1], aPh, bvh[2], bvh[3]);
                mma16816(oacc[2*nt6+1], aPh, bvl[2], bvl[3]);
                mma16816(oacc[2*nt6+1], aPl, bvh[2], bvh[3]);
            }
        }

        // ---- reduce across wn halves + stage + store ----
        if (wn == 1) {
            #pragma unroll
            for (int ct = 0; ct < 12; ct++)
                #pragma unroll
                for (int i = 0; i < 4; i++) {
                    int row = wm*16 + g + 8*(i >> 1);
                    int col = ct*8 + 2*tg + (i & 1);
                    opart[row*96 + col] = oacc[ct][i];
                }
        }
        __syncthreads();
        if (wn == 0) {
            #pragma unroll
            for (int ct = 0; ct < 12; ct++)
                #pragma unroll
                for (int i = 0; i < 4; i++) {
                    int row = wm*16 + g + 8*(i >> 1);
                    int col = ct*8 + 2*tg + (i & 1);
                    ostg[col*66 + row] = oacc[ct][i] + opart[row*96 + col];
                }
        }
        __syncthreads();
        for (int e = tid; e < 96*64; e += 256) {
            int c = e >> 6, i = e & 63;
            int q = qbase + i;
            if (q < WN) ob[(size_t)c*WN + q] = ostg[c*66 + i];
        }
    }
}

// -------------------- window-reverse + roll(+3) + residual + LN2 --------------
__global__ __launch_bounds__(256)
void k_resln2(const float* __restrict__ x,
              const float* __restrict__ gg, const float* __restrict__ bb) {
    __shared__ float xs[32*101];
    int p0 = blockIdx.x * 32;
    int tid = threadIdx.x, lane = tid & 31, wp = tid >> 5;
    for (int e = tid; e < 96*32; e += 256) {
        int c = e >> 5, i = e & 31;
        xs[i*101 + c] = x[(size_t)c*NTOK + p0 + i];
    }
    __syncthreads();
    #pragma unroll
    for (int ii = wp; ii < 32; ii += 8) {
        int p = p0 + ii;
        int s = p / 3136, r = p % 3136, h = r / 56, w = r % 56;
        int s2 = (s >= 3) ? s - 3 : s + 53;
        int h2 = (h >= 3) ? h - 3 : h + 53;
        int w2 = (w >= 3) ? w - 3 : w + 53;
        int win = (s2/7)*64 + (h2/7)*8 + (w2/7);
        int np  = (s2%7)*49 + (h2%7)*7 + (w2%7);
        const float* ov = g_ot + (size_t)win*WN*CDIM + np*96;
        float v0 = xs[ii*101 + lane]      + ov[lane];
        float v1 = xs[ii*101 + lane + 32] + ov[lane + 32];
        float v2 = xs[ii*101 + lane + 64] + ov[lane + 64];
        float* xr = g_xres + (size_t)p*CDIM;
        xr[lane] = v0; xr[lane + 32] = v1; xr[lane + 64] = v2;
        float sum = v0 + v1 + v2, sq = v0*v0 + v1*v1 + v2*v2;
        #pragma unroll
        for (int o = 16; o; o >>= 1) {
            sum += __shfl_xor_sync(0xffffffffu, sum, o);
            sq  += __shfl_xor_sync(0xffffffffu, sq, o);
        }
        float mean = sum * (1.f/96.f);
        float var  = sq * (1.f/96.f) - mean*mean;
        float inv  = rsqrtf(var + 1e-5f);
        size_t yo = (size_t)p*CDIM;
        float y0 = (v0 - mean)*inv*gg[lane]      + bb[lane];
        float y1 = (v1 - mean)*inv*gg[lane + 32] + bb[lane + 32];
        float y2 = (v2 - mean)*inv*gg[lane + 64] + bb[lane + 64];
        bsplit(y0, g_l2h[yo + lane],      g_l2l[yo + lane]);
        bsplit(y1, g_l2h[yo + lane + 32], g_l2l[yo + lane + 32]);
        bsplit(y2, g_l2h[yo + lane + 64], g_l2l[yo + lane + 64]);
    }
}

// -------------------- launch ---------------------------------------------------
extern "C" void kernel_launch(void* const* d_in, const int* in_sizes, int n_in,
                              void* d_out, int out_size) {
    const float* x   = (const float*)d_in[0];
    const float* n1g = (const float*)d_in[1];
    const float* n1b = (const float*)d_in[2];
    const float* wq  = (const float*)d_in[3];
    const float* bq  = (const float*)d_in[4];
    const float* wk  = (const float*)d_in[5];
    const float* bk  = (const float*)d_in[6];
    const float* wv  = (const float*)d_in[7];
    const float* bv  = (const float*)d_in[8];
    const float* dqw = (const float*)d_in[9];
    const float* dqb = (const float*)d_in[10];
    const float* dkw = (const float*)d_in[11];
    const float* dkb = (const float*)d_in[12];
    const float* dvw = (const float*)d_in[13];
    const float* dvb = (const float*)d_in[14];
    const float* n2g = (const float*)d_in[15];
    const float* n2b = (const float*)d_in[16];
    const float* f1w = (const float*)d_in[17];
    const float* f1b = (const float*)d_in[18];
    const float* f2w = (const float*)d_in[19];
    const float* f2b = (const float*)d_in[20];
    float* out = (float*)d_out;

    float *pqp, *pkp, *pvp, *pxres, *pbqkv;
    __nv_bfloat16 *pxwh, *pxwl, *pl2h, *pl2l, *phh, *phl, *pwqh, *pwql, *pf1h, *pf1l, *pf2h, *pf2l;
    __nv_bfloat16 *pqh, *pql_, *pkh, *pkl, *pvh, *pvl;
    cudaGetSymbolAddress((void**)&pqp,  g_qp);
    cudaGetSymbolAddress((void**)&pkp,  g_kp);
    cudaGetSymbolAddress((void**)&pvp,  g_vp);
    cudaGetSymbolAddress((void**)&pxres,g_xres);
    cudaGetSymbolAddress((void**)&pbqkv,g_bqkv);
    cudaGetSymbolAddress((void**)&pxwh, g_xwh);
    cudaGetSymbolAddress((void**)&pxwl, g_xwl);
    cudaGetSymbolAddress((void**)&pl2h, g_l2h);
    cudaGetSymbolAddress((void**)&pl2l, g_l2l);
    cudaGetSymbolAddress((void**)&phh,  g_hh);
    cudaGetSymbolAddress((void**)&phl,  g_hl);
    cudaGetSymbolAddress((void**)&pwqh, g_wqh);
    cudaGetSymbolAddress((void**)&pwql, g_wql);
    cudaGetSymbolAddress((void**)&pf1h, g_f1h);
    cudaGetSymbolAddress((void**)&pf1l, g_f1l);
    cudaGetSymbolAddress((void**)&pf2h, g_f2h);
    cudaGetSymbolAddress((void**)&pf2l, g_f2l);
    cudaGetSymbolAddress((void**)&pqh,  g_qh);
    cudaGetSymbolAddress((void**)&pql_, g_ql);
    cudaGetSymbolAddress((void**)&pkh,  g_kh);
    cudaGetSymbolAddress((void**)&pkl,  g_kl);
    cudaGetSymbolAddress((void**)&pvh,  g_vh);
    cudaGetSymbolAddress((void**)&pvl,  g_vl);

    cudaFuncSetAttribute(k_attn, cudaFuncAttributeMaxDynamicSharedMemorySize, AT_SMEM);
    cudaFuncSetAttribute(k_tgemm<0>, cudaFuncAttributeMaxDynamicSharedMemorySize, TG_SMEM);
    cudaFuncSetAttribute(k_tgemm<1>, cudaFuncAttributeMaxDynamicSharedMemorySize, TG_SMEM);
    cudaFuncSetAttribute(k_tgemm<2>, cudaFuncAttributeMaxDynamicSharedMemorySize, TG_SMEM);

    k_prep1<<<(3*96*96 + 255)/256, 256>>>(wq, bq, wk, bk, wv, bv);
    k_prep2<<<(HIDD*96 + 255)/256, 256>>>(f1w, f2w);
    k_ln1<<<NTOK/64, 256>>>(x, n1g, n1b);

    // qkv: D = xw @ wqkv^T (+bias), A loaded once, 3 N-slices in-kernel
    k_tgemm<0><<<NTOK/128, 256, TG_SMEM>>>(pxwh, pxwl, pwqh, pwql, pbqkv, 96,
                                           pqp, pkp, pvp, nullptr, nullptr, nullptr, nullptr);

    // depthwise -> bf16 hi/lo planes (fused q/k/v)
    dim3 gdw(NW, 3, 3);
    k_dw<<<gdw, 392>>>(pqp, pkp, pvp, dqw, dkw, dvw, dqb, dkb, dvb,
                       pqh, pkh, pvh, pql_, pkl, pvl);

    // tensor-core fused attention (S in registers, fixed 44-bit masks)
    k_attn<<<NW, 256, AT_SMEM>>>(pqh, pql_, pkh, pkl, pvh, pvl);

    k_resln2<<<NTOK/32, 256>>>(x, n2g, n2b);

    // MLP1: GELU(ln2 @ f1w^T + f1b) -> bf16 hi/lo planes, 4 N-slices in-kernel
    k_tgemm<1><<<NTOK/128, 256, TG_SMEM>>>(pl2h, pl2l, pf1h, pf1l, f1b, 96,
                                           nullptr, nullptr, nullptr, phh, phl, nullptr, nullptr);
    // MLP2: out^T = (h @ f2w^T + f2b + xres)
    dim3 g3(NTOK/128, 1);
    k_tgemm<2><<<g3, 256, TG_SMEM>>>(phh, phl, pf2h, pf2l, f2b, HIDD,
                                     nullptr, nullptr, nullptr, nullptr, nullptr, pxres, out);
}

// round 13
// speedup vs baseline: 1.1315x; 1.1315x over previous
#include <cuda_runtime.h>
#include <cuda_bf16.h>
#include <math.h>
#include <stdint.h>

#define NTOK 175616   // 56*56*56
#define CDIM 96
#define NW   512
#define WN   343
#define HIDD 384

typedef unsigned long long u64;
typedef unsigned int u32;
union F4U { float4 f; ulonglong2 u; };

__device__ __forceinline__ u64 ffma2(u64 a, u64 b, u64 c) {
    u64 d; asm("fma.rn.f32x2 %0, %1, %2, %3;" : "=l"(d) : "l"(a), "l"(b), "l"(c));
    return d;
}
__device__ __forceinline__ void bsplit(float v, __nv_bfloat16& h, __nv_bfloat16& l) {
    h = __float2bfloat16_rn(v);
    l = __float2bfloat16_rn(v - __bfloat162float(h));
}
__device__ __forceinline__ u32 pack_bf(__nv_bfloat16 a, __nv_bfloat16 b) {
    return (u32)__bfloat16_as_ushort(a) | ((u32)__bfloat16_as_ushort(b) << 16);
}
__device__ __forceinline__ float gelu_f(float v) {
    return 0.5f * v * (1.f + erff(v * 0.70710678118654752f));
}
__device__ __forceinline__ void mma16816(float* d, const u32* a, u32 b0, u32 b1) {
    asm volatile("mma.sync.aligned.m16n8k16.row.col.f32.bf16.bf16.f32 "
                 "{%0,%1,%2,%3}, {%4,%5,%6,%7}, {%8,%9}, {%0,%1,%2,%3};"
                 : "+f"(d[0]), "+f"(d[1]), "+f"(d[2]), "+f"(d[3])
                 : "r"(a[0]), "r"(a[1]), "r"(a[2]), "r"(a[3]), "r"(b0), "r"(b1));
}
__device__ __forceinline__ void ldmx4(u32* r, const __nv_bfloat16* p) {
    u32 addr = (u32)__cvta_generic_to_shared(p);
    asm volatile("ldmatrix.sync.aligned.m8n8.x4.shared.b16 {%0,%1,%2,%3}, [%4];"
                 : "=r"(r[0]), "=r"(r[1]), "=r"(r[2]), "=r"(r[3]) : "r"(addr));
}
__device__ __forceinline__ void ldmx4t(u32* r, const __nv_bfloat16* p) {
    u32 addr = (u32)__cvta_generic_to_shared(p);
    asm volatile("ldmatrix.sync.aligned.m8n8.x4.trans.shared.b16 {%0,%1,%2,%3}, [%4];"
                 : "=r"(r[0]), "=r"(r[1]), "=r"(r[2]), "=r"(r[3]) : "r"(addr));
}
__device__ __forceinline__ void ldmx2t(u32* r, const __nv_bfloat16* p) {
    u32 addr = (u32)__cvta_generic_to_shared(p);
    asm volatile("ldmatrix.sync.aligned.m8n8.x2.trans.shared.b16 {%0,%1}, [%2];"
                 : "=r"(r[0]), "=r"(r[1]) : "r"(addr));
}

// -------------------- scratch (device globals) -------------------------------
__device__ __nv_bfloat16 g_xwh[(size_t)NTOK*CDIM], g_xwl[(size_t)NTOK*CDIM];
__device__ float g_qp [(size_t)NTOK*CDIM];
__device__ float g_kp [(size_t)NTOK*CDIM];
__device__ float g_vp [(size_t)NTOK*CDIM];
__device__ __nv_bfloat16 g_qh[(size_t)NTOK*CDIM], g_ql[(size_t)NTOK*CDIM];
__device__ __nv_bfloat16 g_kh[(size_t)NTOK*CDIM], g_kl[(size_t)NTOK*CDIM];
__device__ __nv_bfloat16 g_vh[(size_t)NTOK*CDIM], g_vl[(size_t)NTOK*CDIM];
__device__ float g_ot [(size_t)NTOK*CDIM];   // attention out, axis-mixed: flat = c*343 + n
__device__ float g_xres[(size_t)NTOK*CDIM];
__device__ __nv_bfloat16 g_l2h[(size_t)NTOK*CDIM], g_l2l[(size_t)NTOK*CDIM];
__device__ __nv_bfloat16 g_hh[(size_t)NTOK*HIDD], g_hl[(size_t)NTOK*HIDD];
__device__ __nv_bfloat16 g_wqh[288*96], g_wql[288*96];
__device__ __nv_bfloat16 g_f1h[HIDD*96], g_f1l[HIDD*96];
__device__ __nv_bfloat16 g_f2h[96*HIDD], g_f2l[96*HIDD];
__device__ float g_bqkv[288];

// -------------------- weight prep --------------------------------------------
__global__ void k_prep1(const float* __restrict__ wq, const float* __restrict__ bq,
                        const float* __restrict__ wk, const float* __restrict__ bk,
                        const float* __restrict__ wv, const float* __restrict__ bv) {
    int i = blockIdx.x * 256 + threadIdx.x;
    if (i < 3*96*96) {
        int t = i / 9216, r = i % 9216;
        float v = (t == 0) ? wq[r] : (t == 1) ? wk[r] : wv[r];
        bsplit(v, g_wqh[i], g_wql[i]);
    }
    if (i < 288) {
        int t = i / 96, r = i % 96;
        g_bqkv[i] = (t == 0) ? bq[r] : (t == 1) ? bk[r] : bv[r];
    }
}
__global__ void k_prep2(const float* __restrict__ f1w, const float* __restrict__ f2w) {
    int i = blockIdx.x * 256 + threadIdx.x;
    if (i < HIDD*96) {
        bsplit(f1w[i], g_f1h[i], g_f1l[i]);
        bsplit(f2w[i], g_f2h[i], g_f2l[i]);
    }
}

// -------------------- LN1 + roll(-3) + window partition -----------------------
__global__ __launch_bounds__(256)
void k_ln1(const float* __restrict__ x,
           const float* __restrict__ gg, const float* __restrict__ bb) {
    __shared__ float xs[64*101];
    int p0 = blockIdx.x * 64;
    int tid = threadIdx.x, lane = tid & 31, wp = tid >> 5;
    for (int e = tid; e < 96*64; e += 256) {
        int c = e >> 6, i = e & 63;
        xs[i*101 + c] = x[(size_t)c*NTOK + p0 + i];
    }
    __syncthreads();
    #pragma unroll
    for (int ii = wp; ii < 64; ii += 8) {
        int p = p0 + ii;
        int s = p / 3136, r = p % 3136, h = r / 56, w = r % 56;
        int s2 = (s >= 3) ? s - 3 : s + 53;
        int h2 = (h >= 3) ? h - 3 : h + 53;
        int w2 = (w >= 3) ? w - 3 : w + 53;
        int win = (s2/7)*64 + (h2/7)*8 + (w2/7);
        int t   = (s2%7)*49 + (h2%7)*7 + (w2%7);
        float v0 = xs[ii*101 + lane];
        float v1 = xs[ii*101 + lane + 32];
        float v2 = xs[ii*101 + lane + 64];
        float sum = v0 + v1 + v2, sq = v0*v0 + v1*v1 + v2*v2;
        #pragma unroll
        for (int o = 16; o; o >>= 1) {
            sum += __shfl_xor_sync(0xffffffffu, sum, o);
            sq  += __shfl_xor_sync(0xffffffffu, sq, o);
        }
        float mean = sum * (1.f/96.f);
        float var  = sq * (1.f/96.f) - mean*mean;
        float inv  = rsqrtf(var + 1e-5f);
        size_t ob = ((size_t)win*WN + t)*CDIM;
        float y0 = (v0 - mean)*inv*gg[lane]      + bb[lane];
        float y1 = (v1 - mean)*inv*gg[lane + 32] + bb[lane + 32];
        float y2 = (v2 - mean)*inv*gg[lane + 64] + bb[lane + 64];
        bsplit(y0, g_xwh[ob + lane],      g_xwl[ob + lane]);
        bsplit(y1, g_xwh[ob + lane + 32], g_xwl[ob + lane + 32]);
        bsplit(y2, g_xwh[ob + lane + 64], g_xwl[ob + lane + 64]);
    }
}

// -------------------- tensor-core GEMM (bf16 split, mma.sync + ldmatrix) -----
// EPI 0: qkv (K=96, 3 N-slices, A loaded once). EPI 1: MLP1 GELU (K=96, 4 slices).
// EPI 2: MLP2 (K=384 chunked, 1 slice, residual + transposed store).
#define SA_STRIDE 104
#define TG_A_HI 0
#define TG_A_LO (128*104)          // bf16 units
#define TG_B_HI (2*128*104)
#define TG_B_LO (2*128*104 + 96*104)
#define TG_SMEM ((2*128*104 + 2*96*104) * 2)   // 93184 bytes

template<int EPI>
__global__ __launch_bounds__(256, 2)
void k_tgemm(const __nv_bfloat16* __restrict__ Ah, const __nv_bfloat16* __restrict__ Al,
             const __nv_bfloat16* __restrict__ Wh, const __nv_bfloat16* __restrict__ Wl,
             const float* __restrict__ bias, int K,
             float* __restrict__ O0, float* __restrict__ O1, float* __restrict__ O2,
             __nv_bfloat16* __restrict__ Oh, __nv_bfloat16* __restrict__ Ol,
             const float* __restrict__ Res, float* __restrict__ OutT) {
    extern __shared__ char smemc[];
    __nv_bfloat16* sA = (__nv_bfloat16*)smemc;
    int tid = threadIdx.x, lane = tid & 31, wid = tid >> 5;
    int g = lane >> 2, tg = lane & 3;
    int bm = blockIdx.x * 128;
    int warpM = (wid & 3) * 32, warpN = (wid >> 2) * 48;
    int lr = lane & 15;
    int lc = (lane & 16) ? 8 : 0;

    if (EPI == 2) {
        float acc[2][6][4];
        #pragma unroll
        for (int mt = 0; mt < 2; mt++)
            #pragma unroll
            for (int nt = 0; nt < 6; nt++)
                #pragma unroll
                for (int i = 0; i < 4; i++) acc[mt][nt][i] = 0.f;

        int nch = K / 96;
        for (int kc = 0; kc < nch; kc++) {
            const __nv_bfloat16* pAh = Ah + (size_t)bm*K + kc*96;
            const __nv_bfloat16* pAl = Al + (size_t)bm*K + kc*96;
            for (int e = tid; e < 128*24; e += 256) {
                int r = e / 24, c4 = e % 24;
                *(uint2*)(sA + TG_A_HI + r*SA_STRIDE + c4*4) = *(const uint2*)(pAh + (size_t)r*K + c4*4);
                *(uint2*)(sA + TG_A_LO + r*SA_STRIDE + c4*4) = *(const uint2*)(pAl + (size_t)r*K + c4*4);
            }
            const __nv_bfloat16* pWh = Wh + kc*96;
            const __nv_bfloat16* pWl = Wl + kc*96;
            for (int e = tid; e < 96*24; e += 256) {
                int r = e / 24, c4 = e % 24;
                *(uint2*)(sA + TG_B_HI + r*SA_STRIDE + c4*4) = *(const uint2*)(pWh + (size_t)r*K + c4*4);
                *(uint2*)(sA + TG_B_LO + r*SA_STRIDE + c4*4) = *(const uint2*)(pWl + (size_t)r*K + c4*4);
            }
            __syncthreads();
            #pragma unroll
            for (int ks = 0; ks < 6; ks++) {
                int k0 = ks * 16;
                u32 ah[2][4], al_[2][4];
                #pragma unroll
                for (int mt = 0; mt < 2; mt++) {
                    int ro = (warpM + mt*16 + lr)*SA_STRIDE + k0 + lc;
                    ldmx4(ah[mt],  sA + TG_A_HI + ro);
                    ldmx4(al_[mt], sA + TG_A_LO + ro);
                }
                u32 bh[3][4], bl[3][4];
                #pragma unroll
                for (int np = 0; np < 3; np++) {
                    int ro = (warpN + np*16 + lr)*SA_STRIDE + k0 + lc;
                    ldmx4(bh[np], sA + TG_B_HI + ro);
                    ldmx4(bl[np], sA + TG_B_LO + ro);
                }
                #pragma unroll
                for (int np = 0; np < 3; np++) {
                    #pragma unroll
                    for (int mt = 0; mt < 2; mt++) {
                        mma16816(acc[mt][2*np],   ah[mt],  bh[np][0], bh[np][2]);
                        mma16816(acc[mt][2*np+1], ah[mt],  bh[np][1], bh[np][3]);
                        mma16816(acc[mt][2*np],   ah[mt],  bl[np][0], bl[np][2]);
                        mma16816(acc[mt][2*np+1], ah[mt],  bl[np][1], bl[np][3]);
                        mma16816(acc[mt][2*np],   al_[mt], bh[np][0], bh[np][2]);
                        mma16816(acc[mt][2*np+1], al_[mt], bh[np][1], bh[np][3]);
                    }
                }
            }
            __syncthreads();
        }
        float* st = (float*)smemc;    // 96 cols x 132 rows
        #pragma unroll
        for (int mt = 0; mt < 2; mt++) {
            int rl = warpM + mt*16 + g;
            #pragma unroll
            for (int nt = 0; nt < 6; nt++) {
                int c = warpN + nt*8 + 2*tg;
                float b0 = bias[c], b1 = bias[c + 1];
                #pragma unroll
                for (int hrow = 0; hrow < 2; hrow++) {
                    int row = rl + hrow*8;
                    const float* rr = Res + (size_t)(bm + row)*96;
                    st[(c)  *132 + row] = acc[mt][nt][2*hrow]   + b0 + rr[c];
                    st[(c+1)*132 + row] = acc[mt][nt][2*hrow+1] + b1 + rr[c+1];
                }
            }
        }
        __syncthreads();
        for (int e = tid; e < 96*128; e += 256) {
            int col = e >> 7, r = e & 127;
            OutT[(size_t)col*NTOK + bm + r] = st[col*132 + r];
        }
        return;
    }

    // ---- EPI 0 / 1: K = 96, A loaded once, loop over N-slices ----
    {
        const __nv_bfloat16* pAh = Ah + (size_t)bm*96;
        const __nv_bfloat16* pAl = Al + (size_t)bm*96;
        for (int e = tid; e < 128*24; e += 256) {
            int r = e / 24, c4 = e % 24;
            *(uint2*)(sA + TG_A_HI + r*SA_STRIDE + c4*4) = *(const uint2*)(pAh + (size_t)r*96 + c4*4);
            *(uint2*)(sA + TG_A_LO + r*SA_STRIDE + c4*4) = *(const uint2*)(pAl + (size_t)r*96 + c4*4);
        }
        const int NY = (EPI == 0) ? 3 : 4;
        for (int ys = 0; ys < NY; ys++) {
            int bn = ys * 96;
            __syncthreads();     // orders A stores (ys=0) / prior B reads (ys>0)
            const __nv_bfloat16* pWh = Wh + (size_t)bn*96;
            const __nv_bfloat16* pWl = Wl + (size_t)bn*96;
            for (int e = tid; e < 96*24; e += 256) {
                int r = e / 24, c4 = e % 24;
                *(uint2*)(sA + TG_B_HI + r*SA_STRIDE + c4*4) = *(const uint2*)(pWh + (size_t)r*96 + c4*4);
                *(uint2*)(sA + TG_B_LO + r*SA_STRIDE + c4*4) = *(const uint2*)(pWl + (size_t)r*96 + c4*4);
            }
            __syncthreads();

            float acc[2][6][4];
            #pragma unroll
            for (int mt = 0; mt < 2; mt++)
                #pragma unroll
                for (int nt = 0; nt < 6; nt++)
                    #pragma unroll
                    for (int i = 0; i < 4; i++) acc[mt][nt][i] = 0.f;

            #pragma unroll
            for (int ks = 0; ks < 6; ks++) {
                int k0 = ks * 16;
                u32 ah[2][4], al_[2][4];
                #pragma unroll
                for (int mt = 0; mt < 2; mt++) {
                    int ro = (warpM + mt*16 + lr)*SA_STRIDE + k0 + lc;
                    ldmx4(ah[mt],  sA + TG_A_HI + ro);
                    ldmx4(al_[mt], sA + TG_A_LO + ro);
                }
                u32 bh[3][4], bl[3][4];
                #pragma unroll
                for (int np = 0; np < 3; np++) {
                    int ro = (warpN + np*16 + lr)*SA_STRIDE + k0 + lc;
                    ldmx4(bh[np], sA + TG_B_HI + ro);
                    ldmx4(bl[np], sA + TG_B_LO + ro);
                }
                #pragma unroll
                for (int np = 0; np < 3; np++) {
                    #pragma unroll
                    for (int mt = 0; mt < 2; mt++) {
                        mma16816(acc[mt][2*np],   ah[mt],  bh[np][0], bh[np][2]);
                        mma16816(acc[mt][2*np+1], ah[mt],  bh[np][1], bh[np][3]);
                        mma16816(acc[mt][2*np],   ah[mt],  bl[np][0], bl[np][2]);
                        mma16816(acc[mt][2*np+1], ah[mt],  bl[np][1], bl[np][3]);
                        mma16816(acc[mt][2*np],   al_[mt], bh[np][0], bh[np][2]);
                        mma16816(acc[mt][2*np+1], al_[mt], bh[np][1], bh[np][3]);
                    }
                }
            }

            if (EPI == 0) {
                float* O = (ys == 0) ? O0 : (ys == 1) ? O1 : O2;
                #pragma unroll
                for (int mt = 0; mt < 2; mt++) {
                    int r0 = bm + warpM + mt*16 + g;
                    #pragma unroll
                    for (int nt = 0; nt < 6; nt++) {
                        int c = warpN + nt*8 + 2*tg;
                        float b0 = bias[bn + c], b1 = bias[bn + c + 1];
                        *(float2*)(O + (size_t)r0*96 + c)       = make_float2(acc[mt][nt][0] + b0, acc[mt][nt][1] + b1);
                        *(float2*)(O + (size_t)(r0 + 8)*96 + c) = make_float2(acc[mt][nt][2] + b0, acc[mt][nt][3] + b1);
                    }
                }
            } else {
                #pragma unroll
                for (int mt = 0; mt < 2; mt++) {
                    int r0 = bm + warpM + mt*16 + g;
                    #pragma unroll
                    for (int nt = 0; nt < 6; nt++) {
                        int c = warpN + nt*8 + 2*tg;
                        float b0 = bias[bn + c], b1 = bias[bn + c + 1];
                        #pragma unroll
                        for (int hrow = 0; hrow < 2; hrow++) {
                            int row = r0 + hrow*8;
                            float v0 = gelu_f(acc[mt][nt][2*hrow]   + b0);
                            float v1 = gelu_f(acc[mt][nt][2*hrow+1] + b1);
                            __nv_bfloat16 h0, l0, h1, l1;
                            bsplit(v0, h0, l0);
                            bsplit(v1, h1, l1);
                            *(u32*)(Oh + (size_t)row*HIDD + bn + c) = pack_bf(h0, h1);
                            *(u32*)(Ol + (size_t)row*HIDD + bn + c) = pack_bf(l0, l1);
                        }
                    }
                }
            }
        }
    }
}

// -------------------- depthwise 3x3x3 (fused q/k/v, bf16-split output) --------
__global__ __launch_bounds__(392, 2)
void k_dw(const float* __restrict__ In0, const float* __restrict__ In1, const float* __restrict__ In2,
          const float* __restrict__ W0, const float* __restrict__ W1, const float* __restrict__ W2,
          const float* __restrict__ B0, const float* __restrict__ B1, const float* __restrict__ B2,
          __nv_bfloat16* __restrict__ OH0, __nv_bfloat16* __restrict__ OH1, __nv_bfloat16* __restrict__ OH2,
          __nv_bfloat16* __restrict__ OL0, __nv_bfloat16* __restrict__ OL1, __nv_bfloat16* __restrict__ OL2) {
    __shared__ float sin_[WN*32];
    __shared__ float wsm[27*32];
    int z = blockIdx.z;
    const float* In = (z == 0) ? In0 : (z == 1) ? In1 : In2;
    const float* Wt = (z == 0) ? W0  : (z == 1) ? W1  : W2;
    const float* Bi = (z == 0) ? B0  : (z == 1) ? B1  : B2;
    __nv_bfloat16* OutH = (z == 0) ? OH0 : (z == 1) ? OH1 : OH2;
    __nv_bfloat16* OutL = (z == 0) ? OL0 : (z == 1) ? OL1 : OL2;

    int win = blockIdx.x;
    int c0 = blockIdx.y * 32;
    int tid = threadIdx.x;
    const float* inw = In + (size_t)win*WN*CDIM + c0;
    for (int e = tid; e < WN*8; e += 392) {
        int t = e >> 3, c4 = e & 7;
        *(float4*)(sin_ + t*32 + c4*4) = *(const float4*)(inw + t*96 + c4*4);
    }
    for (int e = tid; e < 27*32; e += 392) {
        int k = e >> 5, cc = e & 31;
        wsm[k*32 + cc] = Wt[(c0 + cc)*27 + k];
    }
    __syncthreads();

    int g = tid & 7, dy = (tid >> 3) % 7, dz = tid / 56;
    int cc = g * 4;
    F4U bias4; bias4.f = *(const float4*)(Bi + c0 + cc);
    u64 ax[7], ay[7];
    #pragma unroll
    for (int x = 0; x < 7; x++) { ax[x] = bias4.u.x; ay[x] = bias4.u.y; }

    #pragma unroll
    for (int kd = 0; kd < 3; kd++) {
        int nz = dz + kd - 1;
        if ((unsigned)nz >= 7u) continue;
        #pragma unroll
        for (int kh = 0; kh < 3; kh++) {
            int ny = dy + kh - 1;
            if ((unsigned)ny >= 7u) continue;
            const float* row = sin_ + (nz*49 + ny*7)*32 + cc;
            F4U iv[7];
            #pragma unroll
            for (int x = 0; x < 7; x++) iv[x].f = *(const float4*)(row + x*32);
            const float* wp_ = wsm + (kd*9 + kh*3)*32 + cc;
            F4U w0, w1, w2;
            w0.f = *(const float4*)(wp_);
            w1.f = *(const float4*)(wp_ + 32);
            w2.f = *(const float4*)(wp_ + 64);
            #pragma unroll
            for (int x = 1; x < 7; x++) {
                ax[x] = ffma2(w0.u.x, iv[x-1].u.x, ax[x]);
                ay[x] = ffma2(w0.u.y, iv[x-1].u.y, ay[x]);
            }
            #pragma unroll
            for (int x = 0; x < 7; x++) {
                ax[x] = ffma2(w1.u.x, iv[x].u.x, ax[x]);
                ay[x] = ffma2(w1.u.y, iv[x].u.y, ay[x]);
            }
            #pragma unroll
            for (int x = 0; x < 6; x++) {
                ax[x] = ffma2(w2.u.x, iv[x+1].u.x, ax[x]);
                ay[x] = ffma2(w2.u.y, iv[x+1].u.y, ay[x]);
            }
        }
    }

    size_t ob = (size_t)win*WN*CDIM + (size_t)(dz*49 + dy*7)*96 + c0 + cc;
    #pragma unroll
    for (int x = 0; x < 7; x++) {
        F4U o; o.u.x = ax[x]; o.u.y = ay[x];
        __nv_bfloat16 h0,l0,h1,l1,h2,l2,h3,l3;
        bsplit(o.f.x, h0, l0); bsplit(o.f.y, h1, l1);
        bsplit(o.f.z, h2, l2); bsplit(o.f.w, h3, l3);
        uint2 vh = make_uint2(pack_bf(h0,h1), pack_bf(h2,h3));
        uint2 vl = make_uint2(pack_bf(l0,l1), pack_bf(l2,l3));
        *(uint2*)(OutH + ob + (size_t)x*96) = vh;
        *(uint2*)(OutL + ob + (size_t)x*96) = vl;
    }
}

// -------------------- tensor-core fused attention (R9 version) ----------------
// One block / window, 256 thr (8 warps). q-chunks of 64.
#define AB_KH 0
#define AB_KL 74880
#define AB_QH 149760
#define AB_QL 163072
#define AB_PH 92160
#define AB_PL 138240
#define AB_VH 0
#define AB_VL 36608
#define AT_SMEM 184320

__global__ __launch_bounds__(256, 1)
void k_attn(const __nv_bfloat16* __restrict__ Qh, const __nv_bfloat16* __restrict__ Ql,
            const __nv_bfloat16* __restrict__ Kh, const __nv_bfloat16* __restrict__ Kl,
            const __nv_bfloat16* __restrict__ Vh, const __nv_bfloat16* __restrict__ Vl) {
    extern __shared__ char smb[];
    __nv_bfloat16* kh_s = (__nv_bfloat16*)(smb + AB_KH);
    __nv_bfloat16* kl_s = (__nv_bfloat16*)(smb + AB_KL);
    __nv_bfloat16* qh_s = (__nv_bfloat16*)(smb + AB_QH);
    __nv_bfloat16* ql_s = (__nv_bfloat16*)(smb + AB_QL);
    __nv_bfloat16* ph_s = (__nv_bfloat16*)(smb + AB_PH);
    __nv_bfloat16* pl_s = (__nv_bfloat16*)(smb + AB_PL);
    __nv_bfloat16* vh_s = (__nv_bfloat16*)(smb + AB_VH);
    __nv_bfloat16* vl_s = (__nv_bfloat16*)(smb + AB_VL);
    float* S_s = (float*)smb;
    float* O_s = (float*)smb;

    int win = blockIdx.x;
    int tid = threadIdx.x, lane = tid & 31, wp = tid >> 5;
    int g = lane >> 2, tg = lane & 3;
    int lr = lane & 15, lc = (lane & 16) ? 8 : 0;
    int wm = wp & 1, wn = wp >> 1;      // 2 x 4 warp grid

    const __nv_bfloat16* gqh = Qh + (size_t)win*WN*CDIM;
    const __nv_bfloat16* gql = Ql + (size_t)win*WN*CDIM;
    const __nv_bfloat16* gkh = Kh + (size_t)win*WN*CDIM;
    const __nv_bfloat16* gkl = Kl + (size_t)win*WN*CDIM;
    const __nv_bfloat16* gvh = Vh + (size_t)win*WN*CDIM;
    const __nv_bfloat16* gvl = Vl + (size_t)win*WN*CDIM;
    float* ob = g_ot + (size_t)win*WN*CDIM;

    int ws = win >> 6, hs = (win >> 3) & 7, wd = win & 7;
    bool bz = (ws == 7), bh_ = (hs == 7), bw = (wd == 7);
    const float scale = 0.10206207261596575f;   // 1/sqrt(96)

    unsigned mzm = 0, mhm = 0, mwm = 0, mvm = 0;
    #pragma unroll
    for (int j = 0; j < 11; j++) {
        int m = lane + 32*j;
        if (m < WN) {
            int dzm = m / 49, rm = m % 49, dym = rm / 7, dxm = rm % 7;
            if (dzm < 4) mzm |= 1u << j;
            if (dym < 4) mhm |= 1u << j;
            if (dxm < 4) mwm |= 1u << j;
            mvm |= 1u << j;
        }
    }

    for (int chunk = 0; chunk < 6; chunk++) {
        int qbase = chunk * 64;
        __syncthreads();
        for (int e = tid; e < 343*24; e += 256) {
            int r = e / 24, c4 = e % 24;
            *(uint2*)(kh_s + r*104 + c4*4) = *(const uint2*)(gkh + (size_t)r*96 + c4*4);
            *(uint2*)(kl_s + r*104 + c4*4) = *(const uint2*)(gkl + (size_t)r*96 + c4*4);
        }
        for (int e = tid; e < 64*24; e += 256) {
            int r = e / 24, c4 = e % 24;
            int q = qbase + r;
            uint2 vh = make_uint2(0u, 0u), vl = make_uint2(0u, 0u);
            if (q < WN) {
                vh = *(const uint2*)(gqh + (size_t)q*96 + c4*4);
                vl = *(const uint2*)(gql + (size_t)q*96 + c4*4);
            }
            *(uint2*)(qh_s + r*104 + c4*4) = vh;
            *(uint2*)(ql_s + r*104 + c4*4) = vl;
        }
        __syncthreads();

        // ---- phase S: S[64x352] = Q Kt (3-pass split) ----
        float sacc[2][11][4];
        #pragma unroll
        for (int rt = 0; rt < 2; rt++)
            #pragma unroll
            for (int ct = 0; ct < 11; ct++)
                #pragma unroll
                for (int i = 0; i < 4; i++) sacc[rt][ct][i] = 0.f;

        #pragma unroll
        for (int ks = 0; ks < 6; ks++) {
            int k0 = ks * 16;
            u32 aqh[2][4], aql[2][4];
            #pragma unroll
            for (int rt = 0; rt < 2; rt++) {
                int ro = (wm*32 + rt*16 + lr)*104 + k0 + lc;
                ldmx4(aqh[rt], qh_s + ro);
                ldmx4(aql[rt], ql_s + ro);
            }
            #pragma unroll
            for (int bg = 0; bg < 6; bg++) {
                int n0 = wn*88 + bg*16;
                u32 bh[4], bl[4];
                int ro = (n0 + lr)*104 + k0 + lc;
                ldmx4(bh, kh_s + ro);
                ldmx4(bl, kl_s + ro);
                #pragma unroll
                for (int rt = 0; rt < 2; rt++) {
                    mma16816(sacc[rt][2*bg], aqh[rt], bh[0], bh[2]);
                    mma16816(sacc[rt][2*bg], aqh[rt], bl[0], bl[2]);
                    mma16816(sacc[rt][2*bg], aql[rt], bh[0], bh[2]);
                    if (bg < 5) {
                        mma16816(sacc[rt][2*bg+1], aqh[rt], bh[1], bh[3]);
                        mma16816(sacc[rt][2*bg+1], aqh[rt], bl[1], bl[3]);
                        mma16816(sacc[rt][2*bg+1], aql[rt], bh[1], bh[3]);
                    }
                }
            }
        }
        __syncthreads();   // K dead; S region reuses it

        #pragma unroll
        for (int rt = 0; rt < 2; rt++) {
            int row = wm*32 + rt*16 + g;
            #pragma unroll
            for (int ct = 0; ct < 11; ct++) {
                int col = wn*88 + ct*8 + 2*tg;
                *(float2*)(S_s + row*352 + col)       = make_float2(sacc[rt][ct][0], sacc[rt][ct][1]);
                *(float2*)(S_s + (row + 8)*352 + col) = make_float2(sacc[rt][ct][2], sacc[rt][ct][3]);
            }
        }
        __syncthreads();

        // ---- softmax + P split planes ----
        #pragma unroll
        for (int rr = 0; rr < 8; rr++) {
            int qr = wp*8 + rr;
            int q = qbase + qr;
            __nv_bfloat16* ph = ph_s + qr*360;
            __nv_bfloat16* pl = pl_s + qr*360;
            if (q < WN) {
                int dzq = q / 49, rq = q % 49, dyq = rq / 7, dxq = rq % 7;
                bool gz = dzq < 4, gh = dyq < 4, gw = dxq < 4;
                float sc[11];
                float mx = -1e30f;
                #pragma unroll
                for (int j = 0; j < 11; j++) {
                    float v;
                    if (mvm & (1u << j)) {
                        bool same = (!bz  || (gz == ((mzm >> j) & 1))) &&
                                    (!bh_ || (gh == ((mhm >> j) & 1))) &&
                                    (!bw  || (gw == ((mwm >> j) & 1)));
                        v = S_s[qr*352 + lane + 32*j] * scale + (same ? 0.f : -100.f);
                    } else v = -1e30f;
                    sc[j] = v;
                    mx = fmaxf(mx, v);
                }
                #pragma unroll
                for (int o = 16; o; o >>= 1) mx = fmaxf(mx, __shfl_xor_sync(0xffffffffu, mx, o));
                float ssum = 0.f;
                #pragma unroll
                for (int j = 0; j < 11; j++) { sc[j] = __expf(sc[j] - mx); ssum += sc[j]; }
                #pragma unroll
                for (int o = 16; o; o >>= 1) ssum += __shfl_xor_sync(0xffffffffu, ssum, o);
                float rinv = 1.f / ssum;
                #pragma unroll
                for (int j = 0; j < 11; j++) {
                    int m = lane + 32*j;
                    __nv_bfloat16 h, l;
                    if (mvm & (1u << j)) bsplit(sc[j] * rinv, h, l);
                    else { h = __float2bfloat16(0.f); l = h; }
                    ph[m] = h; pl[m] = l;
                }
            } else {
                __nv_bfloat16 z = __float2bfloat16(0.f);
                #pragma unroll
                for (int j = 0; j < 11; j++) { ph[lane + 32*j] = z; pl[lane + 32*j] = z; }
            }
            if (lane < 8) {
                __nv_bfloat16 z = __float2bfloat16(0.f);
                ph[352 + lane] = z; pl[352 + lane] = z;
            }
        }

        // ---- phase PV: O[64x96] = P V (two V halves) ----
        float oacc[2][3][4];
        #pragma unroll
        for (int rt = 0; rt < 2; rt++)
            #pragma unroll
            for (int ct = 0; ct < 3; ct++)
                #pragma unroll
                for (int i = 0; i < 4; i++) oacc[rt][ct][i] = 0.f;

        for (int hh = 0; hh < 2; hh++) {
            __syncthreads();
            for (int e = tid; e < 176*24; e += 256) {
                int r = e / 24, c4 = e % 24;
                int m = hh*176 + r;
                uint2 vh = make_uint2(0u, 0u), vl = make_uint2(0u, 0u);
                if (m < WN) {
                    vh = *(const uint2*)(gvh + (size_t)m*96 + c4*4);
                    vl = *(const uint2*)(gvl + (size_t)m*96 + c4*4);
                }
                *(uint2*)(vh_s + r*104 + c4*4) = vh;
                *(uint2*)(vl_s + r*104 + c4*4) = vl;
            }
            __syncthreads();

            #pragma unroll
            for (int s = 0; s < 11; s++) {
                int kg = hh*176 + s*16;
                int kv = s*16;
                u32 aph[2][4], apl[2][4];
                #pragma unroll
                for (int rt = 0; rt < 2; rt++) {
                    int ro = (wm*32 + rt*16 + lr)*360 + kg + lc;
                    ldmx4(aph[rt], ph_s + ro);
                    ldmx4(apl[rt], pl_s + ro);
                }
                int n0 = wn*24;
                u32 bvh[6], bvl[6];
                {
                    int ro = (kv + lr)*104 + n0 + lc;
                    ldmx4t(bvh, vh_s + ro);
                    ldmx4t(bvl, vl_s + ro);
                    int ro2 = (kv + lr)*104 + n0 + 16;
                    ldmx2t(bvh + 4, vh_s + ro2);
                    ldmx2t(bvl + 4, vl_s + ro2);
                }
                #pragma unroll
                for (int rt = 0; rt < 2; rt++) {
                    #pragma unroll
                    for (int ct = 0; ct < 3; ct++) {
                        u32 b0h = bvh[2*ct], b1h = bvh[2*ct+1];
                        u32 b0l = bvl[2*ct], b1l = bvl[2*ct+1];
                        mma16816(oacc[rt][ct], aph[rt], b0h, b1h);
                        mma16816(oacc[rt][ct], aph[rt], b0l, b1l);
                        mma16816(oacc[rt][ct], apl[rt], b0h, b1h);
                    }
                }
            }
        }
        __syncthreads();

        #pragma unroll
        for (int rt = 0; rt < 2; rt++) {
            int row = wm*32 + rt*16 + g;
            #pragma unroll
            for (int ct = 0; ct < 3; ct++) {
                int col = wn*24 + ct*8 + 2*tg;
                O_s[(col)  *66 + row]     = oacc[rt][ct][0];
                O_s[(col+1)*66 + row]     = oacc[rt][ct][1];
                O_s[(col)  *66 + row + 8] = oacc[rt][ct][2];
                O_s[(col+1)*66 + row + 8] = oacc[rt][ct][3];
            }
        }
        __syncthreads();
        for (int e = tid; e < 96*64; e += 256) {
            int c = e >> 6, i = e & 63;
            int q = qbase + i;
            if (q < WN) ob[(size_t)c*WN + q] = O_s[c*66 + i];
        }
    }
}

// -------------------- window-reverse + roll(+3) + residual + LN2 --------------
__global__ __launch_bounds__(256)
void k_resln2(const float* __restrict__ x,
              const float* __restrict__ gg, const float* __restrict__ bb) {
    __shared__ float xs[32*101];
    int p0 = blockIdx.x * 32;
    int tid = threadIdx.x, lane = tid & 31, wp = tid >> 5;
    for (int e = tid; e < 96*32; e += 256) {
        int c = e >> 5, i = e & 31;
        xs[i*101 + c] = x[(size_t)c*NTOK + p0 + i];
    }
    __syncthreads();
    #pragma unroll
    for (int ii = wp; ii < 32; ii += 8) {
        int p = p0 + ii;
        int s = p / 3136, r = p % 3136, h = r / 56, w = r % 56;
        int s2 = (s >= 3) ? s - 3 : s + 53;
        int h2 = (h >= 3) ? h - 3 : h + 53;
        int w2 = (w >= 3) ? w - 3 : w + 53;
        int win = (s2/7)*64 + (h2/7)*8 + (w2/7);
        int np  = (s2%7)*49 + (h2%7)*7 + (w2%7);
        const float* ov = g_ot + (size_t)win*WN*CDIM + np*96;
        float v0 = xs[ii*101 + lane]      + ov[lane];
        float v1 = xs[ii*101 + lane + 32] + ov[lane + 32];
        float v2 = xs[ii*101 + lane + 64] + ov[lane + 64];
        float* xr = g_xres + (size_t)p*CDIM;
        xr[lane] = v0; xr[lane + 32] = v1; xr[lane + 64] = v2;
        float sum = v0 + v1 + v2, sq = v0*v0 + v1*v1 + v2*v2;
        #pragma unroll
        for (int o = 16; o; o >>= 1) {
            sum += __shfl_xor_sync(0xffffffffu, sum, o);
            sq  += __shfl_xor_sync(0xffffffffu, sq, o);
        }
        float mean = sum * (1.f/96.f);
        float var  = sq * (1.f/96.f) - mean*mean;
        float inv  = rsqrtf(var + 1e-5f);
        size_t yo = (size_t)p*CDIM;
        float y0 = (v0 - mean)*inv*gg[lane]      + bb[lane];
        float y1 = (v1 - mean)*inv*gg[lane + 32] + bb[lane + 32];
        float y2 = (v2 - mean)*inv*gg[lane + 64] + bb[lane + 64];
        bsplit(y0, g_l2h[yo + lane],      g_l2l[yo + lane]);
        bsplit(y1, g_l2h[yo + lane + 32], g_l2l[yo + lane + 32]);
        bsplit(y2, g_l2h[yo + lane + 64], g_l2l[yo + lane + 64]);
    }
}

// -------------------- launch ---------------------------------------------------
extern "C" void kernel_launch(void* const* d_in, const int* in_sizes, int n_in,
                              void* d_out, int out_size) {
    const float* x   = (const float*)d_in[0];
    const float* n1g = (const float*)d_in[1];
    const float* n1b = (const float*)d_in[2];
    const float* wq  = (const float*)d_in[3];
    const float* bq  = (const float*)d_in[4];
    const float* wk  = (const float*)d_in[5];
    const float* bk  = (const float*)d_in[6];
    const float* wv  = (const float*)d_in[7];
    const float* bv  = (const float*)d_in[8];
    const float* dqw = (const float*)d_in[9];
    const float* dqb = (const float*)d_in[10];
    const float* dkw = (const float*)d_in[11];
    const float* dkb = (const float*)d_in[12];
    const float* dvw = (const float*)d_in[13];
    const float* dvb = (const float*)d_in[14];
    const float* n2g = (const float*)d_in[15];
    const float* n2b = (const float*)d_in[16];
    const float* f1w = (const float*)d_in[17];
    const float* f1b = (const float*)d_in[18];
    const float* f2w = (const float*)d_in[19];
    const float* f2b = (const float*)d_in[20];
    float* out = (float*)d_out;

    float *pqp, *pkp, *pvp, *pxres, *pbqkv;
    __nv_bfloat16 *pxwh, *pxwl, *pl2h, *pl2l, *phh, *phl, *pwqh, *pwql, *pf1h, *pf1l, *pf2h, *pf2l;
    __nv_bfloat16 *pqh, *pql_, *pkh, *pkl, *pvh, *pvl;
    cudaGetSymbolAddress((void**)&pqp,  g_qp);
    cudaGetSymbolAddress((void**)&pkp,  g_kp);
    cudaGetSymbolAddress((void**)&pvp,  g_vp);
    cudaGetSymbolAddress((void**)&pxres,g_xres);
    cudaGetSymbolAddress((void**)&pbqkv,g_bqkv);
    cudaGetSymbolAddress((void**)&pxwh, g_xwh);
    cudaGetSymbolAddress((void**)&pxwl, g_xwl);
    cudaGetSymbolAddress((void**)&pl2h, g_l2h);
    cudaGetSymbolAddress((void**)&pl2l, g_l2l);
    cudaGetSymbolAddress((void**)&phh,  g_hh);
    cudaGetSymbolAddress((void**)&phl,  g_hl);
    cudaGetSymbolAddress((void**)&pwqh, g_wqh);
    cudaGetSymbolAddress((void**)&pwql, g_wql);
    cudaGetSymbolAddress((void**)&pf1h, g_f1h);
    cudaGetSymbolAddress((void**)&pf1l, g_f1l);
    cudaGetSymbolAddress((void**)&pf2h, g_f2h);
    cudaGetSymbolAddress((void**)&pf2l, g_f2l);
    cudaGetSymbolAddress((void**)&pqh,  g_qh);
    cudaGetSymbolAddress((void**)&pql_, g_ql);
    cudaGetSymbolAddress((void**)&pkh,  g_kh);
    cudaGetSymbolAddress((void**)&pkl,  g_kl);
    cudaGetSymbolAddress((void**)&pvh,  g_vh);
    cudaGetSymbolAddress((void**)&pvl,  g_vl);

    cudaFuncSetAttribute(k_attn, cudaFuncAttributeMaxDynamicSharedMemorySize, AT_SMEM);
    cudaFuncSetAttribute(k_tgemm<0>, cudaFuncAttributeMaxDynamicSharedMemorySize, TG_SMEM);
    cudaFuncSetAttribute(k_tgemm<1>, cudaFuncAttributeMaxDynamicSharedMemorySize, TG_SMEM);
    cudaFuncSetAttribute(k_tgemm<2>, cudaFuncAttributeMaxDynamicSharedMemorySize, TG_SMEM);

    k_prep1<<<(3*96*96 + 255)/256, 256>>>(wq, bq, wk, bk, wv, bv);
    k_prep2<<<(HIDD*96 + 255)/256, 256>>>(f1w, f2w);
    k_ln1<<<NTOK/64, 256>>>(x, n1g, n1b);

    // qkv: D = xw @ wqkv^T (+bias), A loaded once, 3 N-slices in-kernel
    k_tgemm<0><<<NTOK/128, 256, TG_SMEM>>>(pxwh, pxwl, pwqh, pwql, pbqkv, 96,
                                           pqp, pkp, pvp, nullptr, nullptr, nullptr, nullptr);

    // depthwise -> bf16 hi/lo planes (fused q/k/v)
    dim3 gdw(NW, 3, 3);
    k_dw<<<gdw, 392>>>(pqp, pkp, pvp, dqw, dkw, dvw, dqb, dkb, dvb,
                       pqh, pkh, pvh, pql_, pkl, pvl);

    // tensor-core fused attention (R9 smem-staged version)
    k_attn<<<NW, 256, AT_SMEM>>>(pqh, pql_, pkh, pkl, pvh, pvl);

    k_resln2<<<NTOK/32, 256>>>(x, n2g, n2b);

    // MLP1: GELU(ln2 @ f1w^T + f1b) -> bf16 hi/lo planes, 4 N-slices in-kernel
    k_tgemm<1><<<NTOK/128, 256, TG_SMEM>>>(pl2h, pl2l, pf1h, pf1l, f1b, 96,
                                           nullptr, nullptr, nullptr, phh, phl, nullptr, nullptr);
    // MLP2: out^T = (h @ f2w^T + f2b + xres)
    dim3 g3(NTOK/128, 1);
    k_tgemm<2><<<g3, 256, TG_SMEM>>>(phh, phl, pf2h, pf2l, f2b, HIDD,
                                     nullptr, nullptr, nullptr, nullptr, nullptr, pxres, out);
}

// round 14
// speedup vs baseline: 1.3459x; 1.1895x over previous
#include <cuda_runtime.h>
#include <cuda_bf16.h>
#include <math.h>
#include <stdint.h>

#define NTOK 175616   // 56*56*56
#define CDIM 96
#define NW   512
#define WN   343
#define HIDD 384

typedef unsigned long long u64;
typedef unsigned int u32;
union F4U { float4 f; ulonglong2 u; };

__device__ __forceinline__ u64 ffma2(u64 a, u64 b, u64 c) {
    u64 d; asm("fma.rn.f32x2 %0, %1, %2, %3;" : "=l"(d) : "l"(a), "l"(b), "l"(c));
    return d;
}
__device__ __forceinline__ void bsplit(float v, __nv_bfloat16& h, __nv_bfloat16& l) {
    h = __float2bfloat16_rn(v);
    l = __float2bfloat16_rn(v - __bfloat162float(h));
}
__device__ __forceinline__ u32 pack_bf(__nv_bfloat16 a, __nv_bfloat16 b) {
    return (u32)__bfloat16_as_ushort(a) | ((u32)__bfloat16_as_ushort(b) << 16);
}
__device__ __forceinline__ float gelu_f(float v) {
    return 0.5f * v * (1.f + erff(v * 0.70710678118654752f));
}
__device__ __forceinline__ void mma16816(float* d, const u32* a, u32 b0, u32 b1) {
    asm volatile("mma.sync.aligned.m16n8k16.row.col.f32.bf16.bf16.f32 "
                 "{%0,%1,%2,%3}, {%4,%5,%6,%7}, {%8,%9}, {%0,%1,%2,%3};"
                 : "+f"(d[0]), "+f"(d[1]), "+f"(d[2]), "+f"(d[3])
                 : "r"(a[0]), "r"(a[1]), "r"(a[2]), "r"(a[3]), "r"(b0), "r"(b1));
}
__device__ __forceinline__ void ldmx4(u32* r, const __nv_bfloat16* p) {
    u32 addr = (u32)__cvta_generic_to_shared(p);
    asm volatile("ldmatrix.sync.aligned.m8n8.x4.shared.b16 {%0,%1,%2,%3}, [%4];"
                 : "=r"(r[0]), "=r"(r[1]), "=r"(r[2]), "=r"(r[3]) : "r"(addr));
}
__device__ __forceinline__ void ldmx4t(u32* r, const __nv_bfloat16* p) {
    u32 addr = (u32)__cvta_generic_to_shared(p);
    asm volatile("ldmatrix.sync.aligned.m8n8.x4.trans.shared.b16 {%0,%1,%2,%3}, [%4];"
                 : "=r"(r[0]), "=r"(r[1]), "=r"(r[2]), "=r"(r[3]) : "r"(addr));
}
__device__ __forceinline__ void ldmx2t(u32* r, const __nv_bfloat16* p) {
    u32 addr = (u32)__cvta_generic_to_shared(p);
    asm volatile("ldmatrix.sync.aligned.m8n8.x2.trans.shared.b16 {%0,%1}, [%2];"
                 : "=r"(r[0]), "=r"(r[1]) : "r"(addr));
}

// -------------------- scratch (device globals) -------------------------------
__device__ __nv_bfloat16 g_xwh[(size_t)NTOK*CDIM];
__device__ float g_qp [(size_t)NTOK*CDIM];
__device__ float g_kp [(size_t)NTOK*CDIM];
__device__ float g_vp [(size_t)NTOK*CDIM];
__device__ __nv_bfloat16 g_qh[(size_t)NTOK*CDIM];
__device__ __nv_bfloat16 g_kh[(size_t)NTOK*CDIM];
__device__ __nv_bfloat16 g_vh[(size_t)NTOK*CDIM];
__device__ float g_ot [(size_t)NTOK*CDIM];   // attention out, axis-mixed: flat = c*343 + n
__device__ float g_xres[(size_t)NTOK*CDIM];
__device__ __nv_bfloat16 g_l2h[(size_t)NTOK*CDIM], g_l2l[(size_t)NTOK*CDIM];
__device__ __nv_bfloat16 g_hh[(size_t)NTOK*HIDD], g_hl[(size_t)NTOK*HIDD];
__device__ __nv_bfloat16 g_wqh[288*96];
__device__ __nv_bfloat16 g_f1h[HIDD*96], g_f1l[HIDD*96];
__device__ __nv_bfloat16 g_f2h[96*HIDD], g_f2l[96*HIDD];
__device__ float g_bqkv[288];

// -------------------- weight prep --------------------------------------------
__global__ void k_prep1(const float* __restrict__ wq, const float* __restrict__ bq,
                        const float* __restrict__ wk, const float* __restrict__ bk,
                        const float* __restrict__ wv, const float* __restrict__ bv) {
    int i = blockIdx.x * 256 + threadIdx.x;
    if (i < 3*96*96) {
        int t = i / 9216, r = i % 9216;
        float v = (t == 0) ? wq[r] : (t == 1) ? wk[r] : wv[r];
        g_wqh[i] = __float2bfloat16_rn(v);
    }
    if (i < 288) {
        int t = i / 96, r = i % 96;
        g_bqkv[i] = (t == 0) ? bq[r] : (t == 1) ? bk[r] : bv[r];
    }
}
__global__ void k_prep2(const float* __restrict__ f1w, const float* __restrict__ f2w) {
    int i = blockIdx.x * 256 + threadIdx.x;
    if (i < HIDD*96) {
        bsplit(f1w[i], g_f1h[i], g_f1l[i]);
        bsplit(f2w[i], g_f2h[i], g_f2l[i]);
    }
}

// -------------------- LN1 + roll(-3) + window partition -----------------------
__global__ __launch_bounds__(256)
void k_ln1(const float* __restrict__ x,
           const float* __restrict__ gg, const float* __restrict__ bb) {
    __shared__ float xs[64*101];
    int p0 = blockIdx.x * 64;
    int tid = threadIdx.x, lane = tid & 31, wp = tid >> 5;
    for (int e = tid; e < 96*64; e += 256) {
        int c = e >> 6, i = e & 63;
        xs[i*101 + c] = x[(size_t)c*NTOK + p0 + i];
    }
    __syncthreads();
    #pragma unroll
    for (int ii = wp; ii < 64; ii += 8) {
        int p = p0 + ii;
        int s = p / 3136, r = p % 3136, h = r / 56, w = r % 56;
        int s2 = (s >= 3) ? s - 3 : s + 53;
        int h2 = (h >= 3) ? h - 3 : h + 53;
        int w2 = (w >= 3) ? w - 3 : w + 53;
        int win = (s2/7)*64 + (h2/7)*8 + (w2/7);
        int t   = (s2%7)*49 + (h2%7)*7 + (w2%7);
        float v0 = xs[ii*101 + lane];
        float v1 = xs[ii*101 + lane + 32];
        float v2 = xs[ii*101 + lane + 64];
        float sum = v0 + v1 + v2, sq = v0*v0 + v1*v1 + v2*v2;
        #pragma unroll
        for (int o = 16; o; o >>= 1) {
            sum += __shfl_xor_sync(0xffffffffu, sum, o);
            sq  += __shfl_xor_sync(0xffffffffu, sq, o);
        }
        float mean = sum * (1.f/96.f);
        float var  = sq * (1.f/96.f) - mean*mean;
        float inv  = rsqrtf(var + 1e-5f);
        size_t ob = ((size_t)win*WN + t)*CDIM;
        g_xwh[ob + lane]      = __float2bfloat16_rn((v0 - mean)*inv*gg[lane]      + bb[lane]);
        g_xwh[ob + lane + 32] = __float2bfloat16_rn((v1 - mean)*inv*gg[lane + 32] + bb[lane + 32]);
        g_xwh[ob + lane + 64] = __float2bfloat16_rn((v2 - mean)*inv*gg[lane + 64] + bb[lane + 64]);
    }
}

// -------------------- tensor-core GEMM (mma.sync + ldmatrix) -----------------
// EPI 0: qkv (K=96, 3 N-slices, single-pass bf16). EPI 1: MLP1 GELU (split, 4 slices).
// EPI 2: MLP2 (split, K=384 chunked, residual + transposed store).
#define SA_STRIDE 104
#define TG_A_HI 0
#define TG_A_LO (128*104)          // bf16 units
#define TG_B_HI (2*128*104)
#define TG_B_LO (2*128*104 + 96*104)
#define TG_SMEM ((2*128*104 + 2*96*104) * 2)   // 93184 bytes

template<int EPI>
__global__ __launch_bounds__(256, 2)
void k_tgemm(const __nv_bfloat16* __restrict__ Ah, const __nv_bfloat16* __restrict__ Al,
             const __nv_bfloat16* __restrict__ Wh, const __nv_bfloat16* __restrict__ Wl,
             const float* __restrict__ bias, int K,
             float* __restrict__ O0, float* __restrict__ O1, float* __restrict__ O2,
             __nv_bfloat16* __restrict__ Oh, __nv_bfloat16* __restrict__ Ol,
             const float* __restrict__ Res, float* __restrict__ OutT) {
    extern __shared__ char smemc[];
    __nv_bfloat16* sA = (__nv_bfloat16*)smemc;
    int tid = threadIdx.x, lane = tid & 31, wid = tid >> 5;
    int g = lane >> 2, tg = lane & 3;
    int bm = blockIdx.x * 128;
    int warpM = (wid & 3) * 32, warpN = (wid >> 2) * 48;
    int lr = lane & 15;
    int lc = (lane & 16) ? 8 : 0;

    if (EPI == 2) {
        float acc[2][6][4];
        #pragma unroll
        for (int mt = 0; mt < 2; mt++)
            #pragma unroll
            for (int nt = 0; nt < 6; nt++)
                #pragma unroll
                for (int i = 0; i < 4; i++) acc[mt][nt][i] = 0.f;

        int nch = K / 96;
        for (int kc = 0; kc < nch; kc++) {
            const __nv_bfloat16* pAh = Ah + (size_t)bm*K + kc*96;
            const __nv_bfloat16* pAl = Al + (size_t)bm*K + kc*96;
            for (int e = tid; e < 128*24; e += 256) {
                int r = e / 24, c4 = e % 24;
                *(uint2*)(sA + TG_A_HI + r*SA_STRIDE + c4*4) = *(const uint2*)(pAh + (size_t)r*K + c4*4);
                *(uint2*)(sA + TG_A_LO + r*SA_STRIDE + c4*4) = *(const uint2*)(pAl + (size_t)r*K + c4*4);
            }
            const __nv_bfloat16* pWh = Wh + kc*96;
            const __nv_bfloat16* pWl = Wl + kc*96;
            for (int e = tid; e < 96*24; e += 256) {
                int r = e / 24, c4 = e % 24;
                *(uint2*)(sA + TG_B_HI + r*SA_STRIDE + c4*4) = *(const uint2*)(pWh + (size_t)r*K + c4*4);
                *(uint2*)(sA + TG_B_LO + r*SA_STRIDE + c4*4) = *(const uint2*)(pWl + (size_t)r*K + c4*4);
            }
            __syncthreads();
            #pragma unroll
            for (int ks = 0; ks < 6; ks++) {
                int k0 = ks * 16;
                u32 ah[2][4], al_[2][4];
                #pragma unroll
                for (int mt = 0; mt < 2; mt++) {
                    int ro = (warpM + mt*16 + lr)*SA_STRIDE + k0 + lc;
                    ldmx4(ah[mt],  sA + TG_A_HI + ro);
                    ldmx4(al_[mt], sA + TG_A_LO + ro);
                }
                u32 bh[3][4], bl[3][4];
                #pragma unroll
                for (int np = 0; np < 3; np++) {
                    int ro = (warpN + np*16 + lr)*SA_STRIDE + k0 + lc;
                    ldmx4(bh[np], sA + TG_B_HI + ro);
                    ldmx4(bl[np], sA + TG_B_LO + ro);
                }
                #pragma unroll
                for (int np = 0; np < 3; np++) {
                    #pragma unroll
                    for (int mt = 0; mt < 2; mt++) {
                        mma16816(acc[mt][2*np],   ah[mt],  bh[np][0], bh[np][2]);
                        mma16816(acc[mt][2*np+1], ah[mt],  bh[np][1], bh[np][3]);
                        mma16816(acc[mt][2*np],   ah[mt],  bl[np][0], bl[np][2]);
                        mma16816(acc[mt][2*np+1], ah[mt],  bl[np][1], bl[np][3]);
                        mma16816(acc[mt][2*np],   al_[mt], bh[np][0], bh[np][2]);
                        mma16816(acc[mt][2*np+1], al_[mt], bh[np][1], bh[np][3]);
                    }
                }
            }
            __syncthreads();
        }
        float* st = (float*)smemc;    // 96 cols x 132 rows
        #pragma unroll
        for (int mt = 0; mt < 2; mt++) {
            int rl = warpM + mt*16 + g;
            #pragma unroll
            for (int nt = 0; nt < 6; nt++) {
                int c = warpN + nt*8 + 2*tg;
                float b0 = bias[c], b1 = bias[c + 1];
                #pragma unroll
                for (int hrow = 0; hrow < 2; hrow++) {
                    int row = rl + hrow*8;
                    const float* rr = Res + (size_t)(bm + row)*96;
                    st[(c)  *132 + row] = acc[mt][nt][2*hrow]   + b0 + rr[c];
                    st[(c+1)*132 + row] = acc[mt][nt][2*hrow+1] + b1 + rr[c+1];
                }
            }
        }
        __syncthreads();
        for (int e = tid; e < 96*128; e += 256) {
            int col = e >> 7, r = e & 127;
            OutT[(size_t)col*NTOK + bm + r] = st[col*132 + r];
        }
        return;
    }

    // ---- EPI 0 / 1: K = 96, A loaded once, loop over N-slices ----
    {
        const __nv_bfloat16* pAh = Ah + (size_t)bm*96;
        const __nv_bfloat16* pAl = Al + (size_t)bm*96;
        for (int e = tid; e < 128*24; e += 256) {
            int r = e / 24, c4 = e % 24;
            *(uint2*)(sA + TG_A_HI + r*SA_STRIDE + c4*4) = *(const uint2*)(pAh + (size_t)r*96 + c4*4);
            if (EPI == 1)
                *(uint2*)(sA + TG_A_LO + r*SA_STRIDE + c4*4) = *(const uint2*)(pAl + (size_t)r*96 + c4*4);
        }
        const int NY = (EPI == 0) ? 3 : 4;
        for (int ys = 0; ys < NY; ys++) {
            int bn = ys * 96;
            __syncthreads();
            const __nv_bfloat16* pWh = Wh + (size_t)bn*96;
            const __nv_bfloat16* pWl = Wl + (size_t)bn*96;
            for (int e = tid; e < 96*24; e += 256) {
                int r = e / 24, c4 = e % 24;
                *(uint2*)(sA + TG_B_HI + r*SA_STRIDE + c4*4) = *(const uint2*)(pWh + (size_t)r*96 + c4*4);
                if (EPI == 1)
                    *(uint2*)(sA + TG_B_LO + r*SA_STRIDE + c4*4) = *(const uint2*)(pWl + (size_t)r*96 + c4*4);
            }
            __syncthreads();

            float acc[2][6][4];
            #pragma unroll
            for (int mt = 0; mt < 2; mt++)
                #pragma unroll
                for (int nt = 0; nt < 6; nt++)
                    #pragma unroll
                    for (int i = 0; i < 4; i++) acc[mt][nt][i] = 0.f;

            #pragma unroll
            for (int ks = 0; ks < 6; ks++) {
                int k0 = ks * 16;
                u32 ah[2][4], al_[2][4];
                #pragma unroll
                for (int mt = 0; mt < 2; mt++) {
                    int ro = (warpM + mt*16 + lr)*SA_STRIDE + k0 + lc;
                    ldmx4(ah[mt], sA + TG_A_HI + ro);
                    if (EPI == 1) ldmx4(al_[mt], sA + TG_A_LO + ro);
                }
                u32 bh[3][4], bl[3][4];
                #pragma unroll
                for (int np = 0; np < 3; np++) {
                    int ro = (warpN + np*16 + lr)*SA_STRIDE + k0 + lc;
                    ldmx4(bh[np], sA + TG_B_HI + ro);
                    if (EPI == 1) ldmx4(bl[np], sA + TG_B_LO + ro);
                }
                #pragma unroll
                for (int np = 0; np < 3; np++) {
                    #pragma unroll
                    for (int mt = 0; mt < 2; mt++) {
                        mma16816(acc[mt][2*np],   ah[mt],  bh[np][0], bh[np][2]);
                        mma16816(acc[mt][2*np+1], ah[mt],  bh[np][1], bh[np][3]);
                        if (EPI == 1) {
                            mma16816(acc[mt][2*np],   ah[mt],  bl[np][0], bl[np][2]);
                            mma16816(acc[mt][2*np+1], ah[mt],  bl[np][1], bl[np][3]);
                            mma16816(acc[mt][2*np],   al_[mt], bh[np][0], bh[np][2]);
                            mma16816(acc[mt][2*np+1], al_[mt], bh[np][1], bh[np][3]);
                        }
                    }
                }
            }

            if (EPI == 0) {
                float* O = (ys == 0) ? O0 : (ys == 1) ? O1 : O2;
                #pragma unroll
                for (int mt = 0; mt < 2; mt++) {
                    int r0 = bm + warpM + mt*16 + g;
                    #pragma unroll
                    for (int nt = 0; nt < 6; nt++) {
                        int c = warpN + nt*8 + 2*tg;
                        float b0 = bias[bn + c], b1 = bias[bn + c + 1];
                        *(float2*)(O + (size_t)r0*96 + c)       = make_float2(acc[mt][nt][0] + b0, acc[mt][nt][1] + b1);
                        *(float2*)(O + (size_t)(r0 + 8)*96 + c) = make_float2(acc[mt][nt][2] + b0, acc[mt][nt][3] + b1);
                    }
                }
            } else {
                #pragma unroll
                for (int mt = 0; mt < 2; mt++) {
                    int r0 = bm + warpM + mt*16 + g;
                    #pragma unroll
                    for (int nt = 0; nt < 6; nt++) {
                        int c = warpN + nt*8 + 2*tg;
                        float b0 = bias[bn + c], b1 = bias[bn + c + 1];
                        #pragma unroll
                        for (int hrow = 0; hrow < 2; hrow++) {
                            int row = r0 + hrow*8;
                            float v0 = gelu_f(acc[mt][nt][2*hrow]   + b0);
                            float v1 = gelu_f(acc[mt][nt][2*hrow+1] + b1);
                            __nv_bfloat16 h0, l0, h1, l1;
                            bsplit(v0, h0, l0);
                            bsplit(v1, h1, l1);
                            *(u32*)(Oh + (size_t)row*HIDD + bn + c) = pack_bf(h0, h1);
                            *(u32*)(Ol + (size_t)row*HIDD + bn + c) = pack_bf(l0, l1);
                        }
                    }
                }
            }
        }
    }
}

// -------------------- depthwise 3x3x3 (fused q/k/v, bf16 output) --------------
__global__ __launch_bounds__(392, 2)
void k_dw(const float* __restrict__ In0, const float* __restrict__ In1, const float* __restrict__ In2,
          const float* __restrict__ W0, const float* __restrict__ W1, const float* __restrict__ W2,
          const float* __restrict__ B0, const float* __restrict__ B1, const float* __restrict__ B2,
          __nv_bfloat16* __restrict__ OH0, __nv_bfloat16* __restrict__ OH1, __nv_bfloat16* __restrict__ OH2) {
    __shared__ float sin_[WN*32];
    __shared__ float wsm[27*32];
    int z = blockIdx.z;
    const float* In = (z == 0) ? In0 : (z == 1) ? In1 : In2;
    const float* Wt = (z == 0) ? W0  : (z == 1) ? W1  : W2;
    const float* Bi = (z == 0) ? B0  : (z == 1) ? B1  : B2;
    __nv_bfloat16* OutH = (z == 0) ? OH0 : (z == 1) ? OH1 : OH2;

    int win = blockIdx.x;
    int c0 = blockIdx.y * 32;
    int tid = threadIdx.x;
    const float* inw = In + (size_t)win*WN*CDIM + c0;
    for (int e = tid; e < WN*8; e += 392) {
        int t = e >> 3, c4 = e & 7;
        *(float4*)(sin_ + t*32 + c4*4) = *(const float4*)(inw + t*96 + c4*4);
    }
    for (int e = tid; e < 27*32; e += 392) {
        int k = e >> 5, cc = e & 31;
        wsm[k*32 + cc] = Wt[(c0 + cc)*27 + k];
    }
    __syncthreads();

    int g = tid & 7, dy = (tid >> 3) % 7, dz = tid / 56;
    int cc = g * 4;
    F4U bias4; bias4.f = *(const float4*)(Bi + c0 + cc);
    u64 ax[7], ay[7];
    #pragma unroll
    for (int x = 0; x < 7; x++) { ax[x] = bias4.u.x; ay[x] = bias4.u.y; }

    #pragma unroll
    for (int kd = 0; kd < 3; kd++) {
        int nz = dz + kd - 1;
        if ((unsigned)nz >= 7u) continue;
        #pragma unroll
        for (int kh = 0; kh < 3; kh++) {
            int ny = dy + kh - 1;
            if ((unsigned)ny >= 7u) continue;
            const float* row = sin_ + (nz*49 + ny*7)*32 + cc;
            F4U iv[7];
            #pragma unroll
            for (int x = 0; x < 7; x++) iv[x].f = *(const float4*)(row + x*32);
            const float* wp_ = wsm + (kd*9 + kh*3)*32 + cc;
            F4U w0, w1, w2;
            w0.f = *(const float4*)(wp_);
            w1.f = *(const float4*)(wp_ + 32);
            w2.f = *(const float4*)(wp_ + 64);
            #pragma unroll
            for (int x = 1; x < 7; x++) {
                ax[x] = ffma2(w0.u.x, iv[x-1].u.x, ax[x]);
                ay[x] = ffma2(w0.u.y, iv[x-1].u.y, ay[x]);
            }
            #pragma unroll
            for (int x = 0; x < 7; x++) {
                ax[x] = ffma2(w1.u.x, iv[x].u.x, ax[x]);
                ay[x] = ffma2(w1.u.y, iv[x].u.y, ay[x]);
            }
            #pragma unroll
            for (int x = 0; x < 6; x++) {
                ax[x] = ffma2(w2.u.x, iv[x+1].u.x, ax[x]);
                ay[x] = ffma2(w2.u.y, iv[x+1].u.y, ay[x]);
            }
        }
    }

    size_t ob = (size_t)win*WN*CDIM + (size_t)(dz*49 + dy*7)*96 + c0 + cc;
    #pragma unroll
    for (int x = 0; x < 7; x++) {
        F4U o; o.u.x = ax[x]; o.u.y = ay[x];
        uint2 vh = make_uint2(
            pack_bf(__float2bfloat16_rn(o.f.x), __float2bfloat16_rn(o.f.y)),
            pack_bf(__float2bfloat16_rn(o.f.z), __float2bfloat16_rn(o.f.w)));
        *(uint2*)(OutH + ob + (size_t)x*96) = vh;
    }
}

// -------------------- tensor-core fused attention (single bf16 plane) ---------
// One block / window, 256 thr (8 warps, 2x4 grid). q-chunks of 64.
// smem: K [352x104 bf16] at 0; Q [64x104] at 73216; P [64x360] at 90112;
//       S fp32 [64x352] overlaps 0.. (K+Q dead); V halves [176x104] at 0;
//       O staging [96x66] f32 at 0.
#define AB_KH 0
#define AB_QH 73216
#define AB_PH 90112
#define AT_SMEM 136192

__global__ __launch_bounds__(256, 1)
void k_attn(const __nv_bfloat16* __restrict__ Qh,
            const __nv_bfloat16* __restrict__ Kh,
            const __nv_bfloat16* __restrict__ Vh) {
    extern __shared__ char smb[];
    __nv_bfloat16* kh_s = (__nv_bfloat16*)(smb + AB_KH);
    __nv_bfloat16* qh_s = (__nv_bfloat16*)(smb + AB_QH);
    __nv_bfloat16* ph_s = (__nv_bfloat16*)(smb + AB_PH);
    __nv_bfloat16* vh_s = (__nv_bfloat16*)(smb + AB_KH);
    float* S_s = (float*)smb;
    float* O_s = (float*)smb;

    int win = blockIdx.x;
    int tid = threadIdx.x, lane = tid & 31, wp = tid >> 5;
    int g = lane >> 2, tg = lane & 3;
    int lr = lane & 15, lc = (lane & 16) ? 8 : 0;
    int wm = wp & 1, wn = wp >> 1;      // 2 x 4 warp grid

    const __nv_bfloat16* gqh = Qh + (size_t)win*WN*CDIM;
    const __nv_bfloat16* gkh = Kh + (size_t)win*WN*CDIM;
    const __nv_bfloat16* gvh = Vh + (size_t)win*WN*CDIM;
    float* ob = g_ot + (size_t)win*WN*CDIM;

    int ws = win >> 6, hs = (win >> 3) & 7, wd = win & 7;
    bool bz = (ws == 7), bh_ = (hs == 7), bw = (wd == 7);
    const float scale = 0.10206207261596575f;   // 1/sqrt(96)

    unsigned mzm = 0, mhm = 0, mwm = 0, mvm = 0;
    #pragma unroll
    for (int j = 0; j < 11; j++) {
        int m = lane + 32*j;
        if (m < WN) {
            int dzm = m / 49, rm = m % 49, dym = rm / 7, dxm = rm % 7;
            if (dzm < 4) mzm |= 1u << j;
            if (dym < 4) mhm |= 1u << j;
            if (dxm < 4) mwm |= 1u << j;
            mvm |= 1u << j;
        }
    }

    for (int chunk = 0; chunk < 6; chunk++) {
        int qbase = chunk * 64;
        __syncthreads();
        for (int e = tid; e < 343*24; e += 256) {
            int r = e / 24, c4 = e % 24;
            *(uint2*)(kh_s + r*104 + c4*4) = *(const uint2*)(gkh + (size_t)r*96 + c4*4);
        }
        for (int e = tid; e < 64*24; e += 256) {
            int r = e / 24, c4 = e % 24;
            int q = qbase + r;
            uint2 vh = make_uint2(0u, 0u);
            if (q < WN) vh = *(const uint2*)(gqh + (size_t)q*96 + c4*4);
            *(uint2*)(qh_s + r*104 + c4*4) = vh;
        }
        __syncthreads();

        // ---- phase S: S[64x352] = Q Kt (single pass) ----
        float sacc[2][11][4];
        #pragma unroll
        for (int rt = 0; rt < 2; rt++)
            #pragma unroll
            for (int ct = 0; ct < 11; ct++)
                #pragma unroll
                for (int i = 0; i < 4; i++) sacc[rt][ct][i] = 0.f;

        #pragma unroll
        for (int ks = 0; ks < 6; ks++) {
            int k0 = ks * 16;
            u32 aqh[2][4];
            #pragma unroll
            for (int rt = 0; rt < 2; rt++) {
                int ro = (wm*32 + rt*16 + lr)*104 + k0 + lc;
                ldmx4(aqh[rt], qh_s + ro);
            }
            #pragma unroll
            for (int bg = 0; bg < 6; bg++) {
                int n0 = wn*88 + bg*16;
                u32 bh[4];
                int ro = (n0 + lr)*104 + k0 + lc;
                ldmx4(bh, kh_s + ro);
                #pragma unroll
                for (int rt = 0; rt < 2; rt++) {
                    mma16816(sacc[rt][2*bg], aqh[rt], bh[0], bh[2]);
                    if (bg < 5)
                        mma16816(sacc[rt][2*bg+1], aqh[rt], bh[1], bh[3]);
                }
            }
        }
        __syncthreads();   // K + Q dead; S region reuses

        #pragma unroll
        for (int rt = 0; rt < 2; rt++) {
            int row = wm*32 + rt*16 + g;
            #pragma unroll
            for (int ct = 0; ct < 11; ct++) {
                int col = wn*88 + ct*8 + 2*tg;
                *(float2*)(S_s + row*352 + col)       = make_float2(sacc[rt][ct][0], sacc[rt][ct][1]);
                *(float2*)(S_s + (row + 8)*352 + col) = make_float2(sacc[rt][ct][2], sacc[rt][ct][3]);
            }
        }
        __syncthreads();

        // ---- softmax + P (single bf16 plane) ----
        #pragma unroll
        for (int rr = 0; rr < 8; rr++) {
            int qr = wp*8 + rr;
            int q = qbase + qr;
            __nv_bfloat16* ph = ph_s + qr*360;
            if (q < WN) {
                int dzq = q / 49, rq = q % 49, dyq = rq / 7, dxq = rq % 7;
                bool gz = dzq < 4, gh = dyq < 4, gw = dxq < 4;
                float sc[11];
                float mx = -1e30f;
                #pragma unroll
                for (int j = 0; j < 11; j++) {
                    float v;
                    if (mvm & (1u << j)) {
                        bool same = (!bz  || (gz == ((mzm >> j) & 1))) &&
                                    (!bh_ || (gh == ((mhm >> j) & 1))) &&
                                    (!bw  || (gw == ((mwm >> j) & 1)));
                        v = S_s[qr*352 + lane + 32*j] * scale + (same ? 0.f : -100.f);
                    } else v = -1e30f;
                    sc[j] = v;
                    mx = fmaxf(mx, v);
                }
                #pragma unroll
                for (int o = 16; o; o >>= 1) mx = fmaxf(mx, __shfl_xor_sync(0xffffffffu, mx, o));
                float ssum = 0.f;
                #pragma unroll
                for (int j = 0; j < 11; j++) { sc[j] = __expf(sc[j] - mx); ssum += sc[j]; }
                #pragma unroll
                for (int o = 16; o; o >>= 1) ssum += __shfl_xor_sync(0xffffffffu, ssum, o);
                float rinv = 1.f / ssum;
                #pragma unroll
                for (int j = 0; j < 11; j++) {
                    int m = lane + 32*j;
                    ph[m] = (mvm & (1u << j)) ? __float2bfloat16_rn(sc[j] * rinv)
                                              : __float2bfloat16(0.f);
                }
            } else {
                __nv_bfloat16 z = __float2bfloat16(0.f);
                #pragma unroll
                for (int j = 0; j < 11; j++) ph[lane + 32*j] = z;
            }
            if (lane < 8) ph[352 + lane] = __float2bfloat16(0.f);
        }

        // ---- phase PV: O[64x96] = P V (two V halves, single pass) ----
        float oacc[2][3][4];
        #pragma unroll
        for (int rt = 0; rt < 2; rt++)
            #pragma unroll
            for (int ct = 0; ct < 3; ct++)
                #pragma unroll
                for (int i = 0; i < 4; i++) oacc[rt][ct][i] = 0.f;

        for (int hh = 0; hh < 2; hh++) {
            __syncthreads();   // S reads done / prev V reads done
            for (int e = tid; e < 176*24; e += 256) {
                int r = e / 24, c4 = e % 24;
                int m = hh*176 + r;
                uint2 vh = make_uint2(0u, 0u);
                if (m < WN) vh = *(const uint2*)(gvh + (size_t)m*96 + c4*4);
                *(uint2*)(vh_s + r*104 + c4*4) = vh;
            }
            __syncthreads();

            #pragma unroll
            for (int s = 0; s < 11; s++) {
                int kg = hh*176 + s*16;
                int kv = s*16;
                u32 aph[2][4];
                #pragma unroll
                for (int rt = 0; rt < 2; rt++) {
                    int ro = (wm*32 + rt*16 + lr)*360 + kg + lc;
                    ldmx4(aph[rt], ph_s + ro);
                }
                int n0 = wn*24;
                u32 bvh[6];
                {
                    int ro = (kv + lr)*104 + n0 + lc;
                    ldmx4t(bvh, vh_s + ro);
                    int ro2 = (kv + lr)*104 + n0 + 16;
                    ldmx2t(bvh + 4, vh_s + ro2);
                }
                #pragma unroll
                for (int rt = 0; rt < 2; rt++) {
                    #pragma unroll
                    for (int ct = 0; ct < 3; ct++)
                        mma16816(oacc[rt][ct], aph[rt], bvh[2*ct], bvh[2*ct+1]);
                }
            }
        }
        __syncthreads();

        #pragma unroll
        for (int rt = 0; rt < 2; rt++) {
            int row = wm*32 + rt*16 + g;
            #pragma unroll
            for (int ct = 0; ct < 3; ct++) {
                int col = wn*24 + ct*8 + 2*tg;
                O_s[(col)  *66 + row]     = oacc[rt][ct][0];
                O_s[(col+1)*66 + row]     = oacc[rt][ct][1];
                O_s[(col)  *66 + row + 8] = oacc[rt][ct][2];
                O_s[(col+1)*66 + row + 8] = oacc[rt][ct][3];
            }
        }
        __syncthreads();
        for (int e = tid; e < 96*64; e += 256) {
            int c = e >> 6, i = e & 63;
            int q = qbase + i;
            if (q < WN) ob[(size_t)c*WN + q] = O_s[c*66 + i];
        }
    }
}

// -------------------- window-reverse + roll(+3) + residual + LN2 --------------
__global__ __launch_bounds__(256)
void k_resln2(const float* __restrict__ x,
              const float* __restrict__ gg, const float* __restrict__ bb) {
    __shared__ float xs[32*101];
    int p0 = blockIdx.x * 32;
    int tid = threadIdx.x, lane = tid & 31, wp = tid >> 5;
    for (int e = tid; e < 96*32; e += 256) {
        int c = e >> 5, i = e & 31;
        xs[i*101 + c] = x[(size_t)c*NTOK + p0 + i];
    }
    __syncthreads();
    #pragma unroll
    for (int ii = wp; ii < 32; ii += 8) {
        int p = p0 + ii;
        int s = p / 3136, r = p % 3136, h = r / 56, w = r % 56;
        int s2 = (s >= 3) ? s - 3 : s + 53;
        int h2 = (h >= 3) ? h - 3 : h + 53;
        int w2 = (w >= 3) ? w - 3 : w + 53;
        int win = (s2/7)*64 + (h2/7)*8 + (w2/7);
        int np  = (s2%7)*49 + (h2%7)*7 + (w2%7);
        const float* ov = g_ot + (size_t)win*WN*CDIM + np*96;
        float v0 = xs[ii*101 + lane]      + ov[lane];
        float v1 = xs[ii*101 + lane + 32] + ov[lane + 32];
        float v2 = xs[ii*101 + lane + 64] + ov[lane + 64];
        float* xr = g_xres + (size_t)p*CDIM;
        xr[lane] = v0; xr[lane + 32] = v1; xr[lane + 64] = v2;
        float sum = v0 + v1 + v2, sq = v0*v0 + v1*v1 + v2*v2;
        #pragma unroll
        for (int o = 16; o; o >>= 1) {
            sum += __shfl_xor_sync(0xffffffffu, sum, o);
            sq  += __shfl_xor_sync(0xffffffffu, sq, o);
        }
        float mean = sum * (1.f/96.f);
        float var  = sq * (1.f/96.f) - mean*mean;
        float inv  = rsqrtf(var + 1e-5f);
        size_t yo = (size_t)p*CDIM;
        float y0 = (v0 - mean)*inv*gg[lane]      + bb[lane];
        float y1 = (v1 - mean)*inv*gg[lane + 32] + bb[lane + 32];
        float y2 = (v2 - mean)*inv*gg[lane + 64] + bb[lane + 64];
        bsplit(y0, g_l2h[yo + lane],      g_l2l[yo + lane]);
        bsplit(y1, g_l2h[yo + lane + 32], g_l2l[yo + lane + 32]);
        bsplit(y2, g_l2h[yo + lane + 64], g_l2l[yo + lane + 64]);
    }
}

// -------------------- launch ---------------------------------------------------
extern "C" void kernel_launch(void* const* d_in, const int* in_sizes, int n_in,
                              void* d_out, int out_size) {
    const float* x   = (const float*)d_in[0];
    const float* n1g = (const float*)d_in[1];
    const float* n1b = (const float*)d_in[2];
    const float* wq  = (const float*)d_in[3];
    const float* bq  = (const float*)d_in[4];
    const float* wk  = (const float*)d_in[5];
    const float* bk  = (const float*)d_in[6];
    const float* wv  = (const float*)d_in[7];
    const float* bv  = (const float*)d_in[8];
    const float* dqw = (const float*)d_in[9];
    const float* dqb = (const float*)d_in[10];
    const float* dkw = (const float*)d_in[11];
    const float* dkb = (const float*)d_in[12];
    const float* dvw = (const float*)d_in[13];
    const float* dvb = (const float*)d_in[14];
    const float* n2g = (const float*)d_in[15];
    const float* n2b = (const float*)d_in[16];
    const float* f1w = (const float*)d_in[17];
    const float* f1b = (const float*)d_in[18];
    const float* f2w = (const float*)d_in[19];
    const float* f2b = (const float*)d_in[20];
    float* out = (float*)d_out;

    float *pqp, *pkp, *pvp, *pxres, *pbqkv;
    __nv_bfloat16 *pxwh, *pl2h, *pl2l, *phh, *phl, *pwqh, *pf1h, *pf1l, *pf2h, *pf2l;
    __nv_bfloat16 *pqh, *pkh, *pvh;
    cudaGetSymbolAddress((void**)&pqp,  g_qp);
    cudaGetSymbolAddress((void**)&pkp,  g_kp);
    cudaGetSymbolAddress((void**)&pvp,  g_vp);
    cudaGetSymbolAddress((void**)&pxres,g_xres);
    cudaGetSymbolAddress((void**)&pbqkv,g_bqkv);
    cudaGetSymbolAddress((void**)&pxwh, g_xwh);
    cudaGetSymbolAddress((void**)&pl2h, g_l2h);
    cudaGetSymbolAddress((void**)&pl2l, g_l2l);
    cudaGetSymbolAddress((void**)&phh,  g_hh);
    cudaGetSymbolAddress((void**)&phl,  g_hl);
    cudaGetSymbolAddress((void**)&pwqh, g_wqh);
    cudaGetSymbolAddress((void**)&pf1h, g_f1h);
    cudaGetSymbolAddress((void**)&pf1l, g_f1l);
    cudaGetSymbolAddress((void**)&pf2h, g_f2h);
    cudaGetSymbolAddress((void**)&pf2l, g_f2l);
    cudaGetSymbolAddress((void**)&pqh,  g_qh);
    cudaGetSymbolAddress((void**)&pkh,  g_kh);
    cudaGetSymbolAddress((void**)&pvh,  g_vh);

    cudaFuncSetAttribute(k_attn, cudaFuncAttributeMaxDynamicSharedMemorySize, AT_SMEM);
    cudaFuncSetAttribute(k_tgemm<0>, cudaFuncAttributeMaxDynamicSharedMemorySize, TG_SMEM);
    cudaFuncSetAttribute(k_tgemm<1>, cudaFuncAttributeMaxDynamicSharedMemorySize, TG_SMEM);
    cudaFuncSetAttribute(k_tgemm<2>, cudaFuncAttributeMaxDynamicSharedMemorySize, TG_SMEM);

    k_prep1<<<(3*96*96 + 255)/256, 256>>>(wq, bq, wk, bk, wv, bv);
    k_prep2<<<(HIDD*96 + 255)/256, 256>>>(f1w, f2w);
    k_ln1<<<NTOK/64, 256>>>(x, n1g, n1b);

    // qkv: D = xw @ wqkv^T (+bias), single-pass bf16, 3 N-slices in-kernel
    k_tgemm<0><<<NTOK/128, 256, TG_SMEM>>>(pxwh, pxwh, pwqh, pwqh, pbqkv, 96,
                                           pqp, pkp, pvp, nullptr, nullptr, nullptr, nullptr);

    // depthwise -> single bf16 plane (fused q/k/v)
    dim3 gdw(NW, 3, 3);
    k_dw<<<gdw, 392>>>(pqp, pkp, pvp, dqw, dkw, dvw, dqb, dkb, dvb,
                       pqh, pkh, pvh);

    // tensor-core fused attention (single bf16 plane)
    k_attn<<<NW, 256, AT_SMEM>>>(pqh, pkh, pvh);

    k_resln2<<<NTOK/32, 256>>>(x, n2g, n2b);

    // MLP1: GELU(ln2 @ f1w^T + f1b) -> bf16 hi/lo planes, 4 N-slices in-kernel
    k_tgemm<1><<<NTOK/128, 256, TG_SMEM>>>(pl2h, pl2l, pf1h, pf1l, f1b, 96,
                                           nullptr, nullptr, nullptr, phh, phl, nullptr, nullptr);
    // MLP2: out^T = (h @ f2w^T + f2b + xres)
    dim3 g3(NTOK/128, 1);
    k_tgemm<2><<<g3, 256, TG_SMEM>>>(phh, phl, pf2h, pf2l, f2b, HIDD,
                                     nullptr, nullptr, nullptr, nullptr, nullptr, pxres, out);
}

// round 17
// speedup vs baseline: 1.4809x; 1.1003x over previous
#include <cuda_runtime.h>
#include <cuda_bf16.h>
#include <cuda_fp16.h>
#include <math.h>
#include <stdint.h>

#define NTOK 175616   // 56*56*56
#define CDIM 96
#define NW   512
#define WN   343
#define HIDD 384

typedef unsigned long long u64;
typedef unsigned int u32;
union F4U { float4 f; ulonglong2 u; };

__device__ __forceinline__ u64 ffma2(u64 a, u64 b, u64 c) {
    u64 d; asm("fma.rn.f32x2 %0, %1, %2, %3;" : "=l"(d) : "l"(a), "l"(b), "l"(c));
    return d;
}
__device__ __forceinline__ void bsplit(float v, __nv_bfloat16& h, __nv_bfloat16& l) {
    h = __float2bfloat16_rn(v);
    l = __float2bfloat16_rn(v - __bfloat162float(h));
}
__device__ __forceinline__ u32 pack_bf(__nv_bfloat16 a, __nv_bfloat16 b) {
    return (u32)__bfloat16_as_ushort(a) | ((u32)__bfloat16_as_ushort(b) << 16);
}
__device__ __forceinline__ float gelu_f(float v) {
    return 0.5f * v * (1.f + erff(v * 0.70710678118654752f));
}
__device__ __forceinline__ void mma16816(float* d, const u32* a, u32 b0, u32 b1) {
    asm volatile("mma.sync.aligned.m16n8k16.row.col.f32.bf16.bf16.f32 "
                 "{%0,%1,%2,%3}, {%4,%5,%6,%7}, {%8,%9}, {%0,%1,%2,%3};"
                 : "+f"(d[0]), "+f"(d[1]), "+f"(d[2]), "+f"(d[3])
                 : "r"(a[0]), "r"(a[1]), "r"(a[2]), "r"(a[3]), "r"(b0), "r"(b1));
}
__device__ __forceinline__ void ldmx4(u32* r, const __nv_bfloat16* p) {
    u32 addr = (u32)__cvta_generic_to_shared(p);
    asm volatile("ldmatrix.sync.aligned.m8n8.x4.shared.b16 {%0,%1,%2,%3}, [%4];"
                 : "=r"(r[0]), "=r"(r[1]), "=r"(r[2]), "=r"(r[3]) : "r"(addr));
}
__device__ __forceinline__ void ldmx4t(u32* r, const __nv_bfloat16* p) {
    u32 addr = (u32)__cvta_generic_to_shared(p);
    asm volatile("ldmatrix.sync.aligned.m8n8.x4.trans.shared.b16 {%0,%1,%2,%3}, [%4];"
                 : "=r"(r[0]), "=r"(r[1]), "=r"(r[2]), "=r"(r[3]) : "r"(addr));
}
__device__ __forceinline__ void ldmx2t(u32* r, const __nv_bfloat16* p) {
    u32 addr = (u32)__cvta_generic_to_shared(p);
    asm volatile("ldmatrix.sync.aligned.m8n8.x2.trans.shared.b16 {%0,%1}, [%2];"
                 : "=r"(r[0]), "=r"(r[1]) : "r"(addr));
}

// -------------------- scratch (device globals) -------------------------------
__device__ __nv_bfloat16 g_xwh[(size_t)NTOK*CDIM];
__device__ float g_qp [(size_t)NTOK*CDIM];
__device__ float g_kp [(size_t)NTOK*CDIM];
__device__ float g_vp [(size_t)NTOK*CDIM];
__device__ __nv_bfloat16 g_qh[(size_t)NTOK*CDIM];
__device__ __nv_bfloat16 g_kh[(size_t)NTOK*CDIM];
__device__ __nv_bfloat16 g_vh[(size_t)NTOK*CDIM];
__device__ float g_ot [(size_t)NTOK*CDIM];   // attention out, axis-mixed: flat = c*343 + n
__device__ float g_xres[(size_t)NTOK*CDIM];
__device__ __nv_bfloat16 g_l2h[(size_t)NTOK*CDIM], g_l2l[(size_t)NTOK*CDIM];
__device__ __nv_bfloat16 g_hh[(size_t)NTOK*HIDD], g_hl[(size_t)NTOK*HIDD];
__device__ __nv_bfloat16 g_wqh[288*96];
__device__ __nv_bfloat16 g_f1h[HIDD*96], g_f1l[HIDD*96];
__device__ __nv_bfloat16 g_f2h[96*HIDD], g_f2l[96*HIDD];
__device__ float g_bqkv[288];

// -------------------- weight prep --------------------------------------------
__global__ void k_prep1(const float* __restrict__ wq, const float* __restrict__ bq,
                        const float* __restrict__ wk, const float* __restrict__ bk,
                        const float* __restrict__ wv, const float* __restrict__ bv) {
    int i = blockIdx.x * 256 + threadIdx.x;
    if (i < 3*96*96) {
        int t = i / 9216, r = i % 9216;
        float v = (t == 0) ? wq[r] : (t == 1) ? wk[r] : wv[r];
        g_wqh[i] = __float2bfloat16_rn(v);
    }
    if (i < 288) {
        int t = i / 96, r = i % 96;
        g_bqkv[i] = (t == 0) ? bq[r] : (t == 1) ? bk[r] : bv[r];
    }
}
__global__ void k_prep2(const float* __restrict__ f1w, const float* __restrict__ f2w) {
    int i = blockIdx.x * 256 + threadIdx.x;
    if (i < HIDD*96) {
        bsplit(f1w[i], g_f1h[i], g_f1l[i]);
        bsplit(f2w[i], g_f2h[i], g_f2l[i]);
    }
}

// -------------------- LN1 + roll(-3) + window partition -----------------------
__global__ __launch_bounds__(256)
void k_ln1(const float* __restrict__ x,
           const float* __restrict__ gg, const float* __restrict__ bb) {
    __shared__ float xs[64*101];
    int p0 = blockIdx.x * 64;
    int tid = threadIdx.x, lane = tid & 31, wp = tid >> 5;
    for (int e = tid; e < 96*64; e += 256) {
        int c = e >> 6, i = e & 63;
        xs[i*101 + c] = x[(size_t)c*NTOK + p0 + i];
    }
    __syncthreads();
    #pragma unroll
    for (int ii = wp; ii < 64; ii += 8) {
        int p = p0 + ii;
        int s = p / 3136, r = p % 3136, h = r / 56, w = r % 56;
        int s2 = (s >= 3) ? s - 3 : s + 53;
        int h2 = (h >= 3) ? h - 3 : h + 53;
        int w2 = (w >= 3) ? w - 3 : w + 53;
        int win = (s2/7)*64 + (h2/7)*8 + (w2/7);
        int t   = (s2%7)*49 + (h2%7)*7 + (w2%7);
        float v0 = xs[ii*101 + lane];
        float v1 = xs[ii*101 + lane + 32];
        float v2 = xs[ii*101 + lane + 64];
        float sum = v0 + v1 + v2, sq = v0*v0 + v1*v1 + v2*v2;
        #pragma unroll
        for (int o = 16; o; o >>= 1) {
            sum += __shfl_xor_sync(0xffffffffu, sum, o);
            sq  += __shfl_xor_sync(0xffffffffu, sq, o);
        }
        float mean = sum * (1.f/96.f);
        float var  = sq * (1.f/96.f) - mean*mean;
        float inv  = rsqrtf(var + 1e-5f);
        size_t ob = ((size_t)win*WN + t)*CDIM;
        g_xwh[ob + lane]      = __float2bfloat16_rn((v0 - mean)*inv*gg[lane]      + bb[lane]);
        g_xwh[ob + lane + 32] = __float2bfloat16_rn((v1 - mean)*inv*gg[lane + 32] + bb[lane + 32]);
        g_xwh[ob + lane + 64] = __float2bfloat16_rn((v2 - mean)*inv*gg[lane + 64] + bb[lane + 64]);
    }
}

// -------------------- tensor-core GEMM (mma.sync + ldmatrix) -----------------
// EPI 0: qkv (K=96, 3 N-slices, single-pass bf16). EPI 1: MLP1 GELU (split, 4 slices).
// EPI 2: MLP2 (split, K=384 chunked, residual + transposed store).
#define SA_STRIDE 104
#define TG_A_HI 0
#define TG_A_LO (128*104)          // bf16 units
#define TG_B_HI (2*128*104)
#define TG_B_LO (2*128*104 + 96*104)
#define TG_SMEM ((2*128*104 + 2*96*104) * 2)   // 93184 bytes

template<int EPI>
__global__ __launch_bounds__(256, 2)
void k_tgemm(const __nv_bfloat16* __restrict__ Ah, const __nv_bfloat16* __restrict__ Al,
             const __nv_bfloat16* __restrict__ Wh, const __nv_bfloat16* __restrict__ Wl,
             const float* __restrict__ bias, int K,
             float* __restrict__ O0, float* __restrict__ O1, float* __restrict__ O2,
             __nv_bfloat16* __restrict__ Oh, __nv_bfloat16* __restrict__ Ol,
             const float* __restrict__ Res, float* __restrict__ OutT) {
    extern __shared__ char smemc[];
    __nv_bfloat16* sA = (__nv_bfloat16*)smemc;
    int tid = threadIdx.x, lane = tid & 31, wid = tid >> 5;
    int g = lane >> 2, tg = lane & 3;
    int bm = blockIdx.x * 128;
    int warpM = (wid & 3) * 32, warpN = (wid >> 2) * 48;
    int lr = lane & 15;
    int lc = (lane & 16) ? 8 : 0;

    if (EPI == 2) {
        float acc[2][6][4];
        #pragma unroll
        for (int mt = 0; mt < 2; mt++)
            #pragma unroll
            for (int nt = 0; nt < 6; nt++)
                #pragma unroll
                for (int i = 0; i < 4; i++) acc[mt][nt][i] = 0.f;

        int nch = K / 96;
        for (int kc = 0; kc < nch; kc++) {
            const __nv_bfloat16* pAh = Ah + (size_t)bm*K + kc*96;
            const __nv_bfloat16* pAl = Al + (size_t)bm*K + kc*96;
            for (int e = tid; e < 128*24; e += 256) {
                int r = e / 24, c4 = e % 24;
                *(uint2*)(sA + TG_A_HI + r*SA_STRIDE + c4*4) = *(const uint2*)(pAh + (size_t)r*K + c4*4);
                *(uint2*)(sA + TG_A_LO + r*SA_STRIDE + c4*4) = *(const uint2*)(pAl + (size_t)r*K + c4*4);
            }
            const __nv_bfloat16* pWh = Wh + kc*96;
            const __nv_bfloat16* pWl = Wl + kc*96;
            for (int e = tid; e < 96*24; e += 256) {
                int r = e / 24, c4 = e % 24;
                *(uint2*)(sA + TG_B_HI + r*SA_STRIDE + c4*4) = *(const uint2*)(pWh + (size_t)r*K + c4*4);
                *(uint2*)(sA + TG_B_LO + r*SA_STRIDE + c4*4) = *(const uint2*)(pWl + (size_t)r*K + c4*4);
            }
            __syncthreads();
            #pragma unroll
            for (int ks = 0; ks < 6; ks++) {
                int k0 = ks * 16;
                u32 ah[2][4], al_[2][4];
                #pragma unroll
                for (int mt = 0; mt < 2; mt++) {
                    int ro = (warpM + mt*16 + lr)*SA_STRIDE + k0 + lc;
                    ldmx4(ah[mt],  sA + TG_A_HI + ro);
                    ldmx4(al_[mt], sA + TG_A_LO + ro);
                }
                u32 bh[3][4], bl[3][4];
                #pragma unroll
                for (int np = 0; np < 3; np++) {
                    int ro = (warpN + np*16 + lr)*SA_STRIDE + k0 + lc;
                    ldmx4(bh[np], sA + TG_B_HI + ro);
                    ldmx4(bl[np], sA + TG_B_LO + ro);
                }
                #pragma unroll
                for (int np = 0; np < 3; np++) {
                    #pragma unroll
                    for (int mt = 0; mt < 2; mt++) {
                        mma16816(acc[mt][2*np],   ah[mt],  bh[np][0], bh[np][2]);
                        mma16816(acc[mt][2*np+1], ah[mt],  bh[np][1], bh[np][3]);
                        mma16816(acc[mt][2*np],   ah[mt],  bl[np][0], bl[np][2]);
                        mma16816(acc[mt][2*np+1], ah[mt],  bl[np][1], bl[np][3]);
                        mma16816(acc[mt][2*np],   al_[mt], bh[np][0], bh[np][2]);
                        mma16816(acc[mt][2*np+1], al_[mt], bh[np][1], bh[np][3]);
                    }
                }
            }
            __syncthreads();
        }
        float* st = (float*)smemc;    // 96 cols x 132 rows
        #pragma unroll
        for (int mt = 0; mt < 2; mt++) {
            int rl = warpM + mt*16 + g;
            #pragma unroll
            for (int nt = 0; nt < 6; nt++) {
                int c = warpN + nt*8 + 2*tg;
                float b0 = bias[c], b1 = bias[c + 1];
                #pragma unroll
                for (int hrow = 0; hrow < 2; hrow++) {
                    int row = rl + hrow*8;
                    const float* rr = Res + (size_t)(bm + row)*96;
                    st[(c)  *132 + row] = acc[mt][nt][2*hrow]   + b0 + rr[c];
                    st[(c+1)*132 + row] = acc[mt][nt][2*hrow+1] + b1 + rr[c+1];
                }
            }
        }
        __syncthreads();
        for (int e = tid; e < 96*128; e += 256) {
            int col = e >> 7, r = e & 127;
            OutT[(size_t)col*NTOK + bm + r] = st[col*132 + r];
        }
        return;
    }

    // ---- EPI 0 / 1: K = 96, A loaded once, loop over N-slices ----
    {
        const __nv_bfloat16* pAh = Ah + (size_t)bm*96;
        const __nv_bfloat16* pAl = Al + (size_t)bm*96;
        for (int e = tid; e < 128*24; e += 256) {
            int r = e / 24, c4 = e % 24;
            *(uint2*)(sA + TG_A_HI + r*SA_STRIDE + c4*4) = *(const uint2*)(pAh + (size_t)r*96 + c4*4);
            if (EPI == 1)
                *(uint2*)(sA + TG_A_LO + r*SA_STRIDE + c4*4) = *(const uint2*)(pAl + (size_t)r*96 + c4*4);
        }
        const int NY = (EPI == 0) ? 3 : 4;
        for (int ys = 0; ys < NY; ys++) {
            int bn = ys * 96;
            __syncthreads();
            const __nv_bfloat16* pWh = Wh + (size_t)bn*96;
            const __nv_bfloat16* pWl = Wl + (size_t)bn*96;
            for (int e = tid; e < 96*24; e += 256) {
                int r = e / 24, c4 = e % 24;
                *(uint2*)(sA + TG_B_HI + r*SA_STRIDE + c4*4) = *(const uint2*)(pWh + (size_t)r*96 + c4*4);
                if (EPI == 1)
                    *(uint2*)(sA + TG_B_LO + r*SA_STRIDE + c4*4) = *(const uint2*)(pWl + (size_t)r*96 + c4*4);
            }
            __syncthreads();

            float acc[2][6][4];
            #pragma unroll
            for (int mt = 0; mt < 2; mt++)
                #pragma unroll
                for (int nt = 0; nt < 6; nt++)
                    #pragma unroll
                    for (int i = 0; i < 4; i++) acc[mt][nt][i] = 0.f;

            #pragma unroll
            for (int ks = 0; ks < 6; ks++) {
                int k0 = ks * 16;
                u32 ah[2][4], al_[2][4];
                #pragma unroll
                for (int mt = 0; mt < 2; mt++) {
                    int ro = (warpM + mt*16 + lr)*SA_STRIDE + k0 + lc;
                    ldmx4(ah[mt], sA + TG_A_HI + ro);
                    if (EPI == 1) ldmx4(al_[mt], sA + TG_A_LO + ro);
                }
                u32 bh[3][4], bl[3][4];
                #pragma unroll
                for (int np = 0; np < 3; np++) {
                    int ro = (warpN + np*16 + lr)*SA_STRIDE + k0 + lc;
                    ldmx4(bh[np], sA + TG_B_HI + ro);
                    if (EPI == 1) ldmx4(bl[np], sA + TG_B_LO + ro);
                }
                #pragma unroll
                for (int np = 0; np < 3; np++) {
                    #pragma unroll
                    for (int mt = 0; mt < 2; mt++) {
                        mma16816(acc[mt][2*np],   ah[mt],  bh[np][0], bh[np][2]);
                        mma16816(acc[mt][2*np+1], ah[mt],  bh[np][1], bh[np][3]);
                        if (EPI == 1) {
                            mma16816(acc[mt][2*np],   ah[mt],  bl[np][0], bl[np][2]);
                            mma16816(acc[mt][2*np+1], ah[mt],  bl[np][1], bl[np][3]);
                            mma16816(acc[mt][2*np],   al_[mt], bh[np][0], bh[np][2]);
                            mma16816(acc[mt][2*np+1], al_[mt], bh[np][1], bh[np][3]);
                        }
                    }
                }
            }

            if (EPI == 0) {
                float* O = (ys == 0) ? O0 : (ys == 1) ? O1 : O2;
                #pragma unroll
                for (int mt = 0; mt < 2; mt++) {
                    int r0 = bm + warpM + mt*16 + g;
                    #pragma unroll
                    for (int nt = 0; nt < 6; nt++) {
                        int c = warpN + nt*8 + 2*tg;
                        float b0 = bias[bn + c], b1 = bias[bn + c + 1];
                        *(float2*)(O + (size_t)r0*96 + c)       = make_float2(acc[mt][nt][0] + b0, acc[mt][nt][1] + b1);
                        *(float2*)(O + (size_t)(r0 + 8)*96 + c) = make_float2(acc[mt][nt][2] + b0, acc[mt][nt][3] + b1);
                    }
                }
            } else {
                #pragma unroll
                for (int mt = 0; mt < 2; mt++) {
                    int r0 = bm + warpM + mt*16 + g;
                    #pragma unroll
                    for (int nt = 0; nt < 6; nt++) {
                        int c = warpN + nt*8 + 2*tg;
                        float b0 = bias[bn + c], b1 = bias[bn + c + 1];
                        #pragma unroll
                        for (int hrow = 0; hrow < 2; hrow++) {
                            int row = r0 + hrow*8;
                            float v0 = gelu_f(acc[mt][nt][2*hrow]   + b0);
                            float v1 = gelu_f(acc[mt][nt][2*hrow+1] + b1);
                            __nv_bfloat16 h0, l0, h1, l1;
                            bsplit(v0, h0, l0);
                            bsplit(v1, h1, l1);
                            *(u32*)(Oh + (size_t)row*HIDD + bn + c) = pack_bf(h0, h1);
                            *(u32*)(Ol + (size_t)row*HIDD + bn + c) = pack_bf(l0, l1);
                        }
                    }
                }
            }
        }
    }
}

// -------------------- depthwise 3x3x3 (fused q/k/v, bf16 output) --------------
__global__ __launch_bounds__(392, 2)
void k_dw(const float* __restrict__ In0, const float* __restrict__ In1, const float* __restrict__ In2,
          const float* __restrict__ W0, const float* __restrict__ W1, const float* __restrict__ W2,
          const float* __restrict__ B0, const float* __restrict__ B1, const float* __restrict__ B2,
          __nv_bfloat16* __restrict__ OH0, __nv_bfloat16* __restrict__ OH1, __nv_bfloat16* __restrict__ OH2) {
    __shared__ float sin_[WN*32];
    __shared__ float wsm[27*32];
    int z = blockIdx.z;
    const float* In = (z == 0) ? In0 : (z == 1) ? In1 : In2;
    const float* Wt = (z == 0) ? W0  : (z == 1) ? W1  : W2;
    const float* Bi = (z == 0) ? B0  : (z == 1) ? B1  : B2;
    __nv_bfloat16* OutH = (z == 0) ? OH0 : (z == 1) ? OH1 : OH2;

    int win = blockIdx.x;
    int c0 = blockIdx.y * 32;
    int tid = threadIdx.x;
    const float* inw = In + (size_t)win*WN*CDIM + c0;
    for (int e = tid; e < WN*8; e += 392) {
        int t = e >> 3, c4 = e & 7;
        *(float4*)(sin_ + t*32 + c4*4) = *(const float4*)(inw + t*96 + c4*4);
    }
    for (int e = tid; e < 27*32; e += 392) {
        int k = e >> 5, cc = e & 31;
        wsm[k*32 + cc] = Wt[(c0 + cc)*27 + k];
    }
    __syncthreads();

    int g = tid & 7, dy = (tid >> 3) % 7, dz = tid / 56;
    int cc = g * 4;
    F4U bias4; bias4.f = *(const float4*)(Bi + c0 + cc);
    u64 ax[7], ay[7];
    #pragma unroll
    for (int x = 0; x < 7; x++) { ax[x] = bias4.u.x; ay[x] = bias4.u.y; }

    #pragma unroll
    for (int kd = 0; kd < 3; kd++) {
        int nz = dz + kd - 1;
        if ((unsigned)nz >= 7u) continue;
        #pragma unroll
        for (int kh = 0; kh < 3; kh++) {
            int ny = dy + kh - 1;
            if ((unsigned)ny >= 7u) continue;
            const float* row = sin_ + (nz*49 + ny*7)*32 + cc;
            F4U iv[7];
            #pragma unroll
            for (int x = 0; x < 7; x++) iv[x].f = *(const float4*)(row + x*32);
            const float* wp_ = wsm + (kd*9 + kh*3)*32 + cc;
            F4U w0, w1, w2;
            w0.f = *(const float4*)(wp_);
            w1.f = *(const float4*)(wp_ + 32);
            w2.f = *(const float4*)(wp_ + 64);
            #pragma unroll
            for (int x = 1; x < 7; x++) {
                ax[x] = ffma2(w0.u.x, iv[x-1].u.x, ax[x]);
                ay[x] = ffma2(w0.u.y, iv[x-1].u.y, ay[x]);
            }
            #pragma unroll
            for (int x = 0; x < 7; x++) {
                ax[x] = ffma2(w1.u.x, iv[x].u.x, ax[x]);
                ay[x] = ffma2(w1.u.y, iv[x].u.y, ay[x]);
            }
            #pragma unroll
            for (int x = 0; x < 6; x++) {
                ax[x] = ffma2(w2.u.x, iv[x+1].u.x, ax[x]);
                ay[x] = ffma2(w2.u.y, iv[x+1].u.y, ay[x]);
            }
        }
    }

    size_t ob = (size_t)win*WN*CDIM + (size_t)(dz*49 + dy*7)*96 + c0 + cc;
    #pragma unroll
    for (int x = 0; x < 7; x++) {
        F4U o; o.u.x = ax[x]; o.u.y = ay[x];
        uint2 vh = make_uint2(
            pack_bf(__float2bfloat16_rn(o.f.x), __float2bfloat16_rn(o.f.y)),
            pack_bf(__float2bfloat16_rn(o.f.z), __float2bfloat16_rn(o.f.w)));
        *(uint2*)(OutH + ob + (size_t)x*96) = vh;
    }
}

// -------------------- tensor-core fused attention (K/V resident) --------------
// One block / window, 256 thr (8 warps, 2x4 grid). q-chunks of 64.
// smem: K[360x104 bf16] @0; V[352x104 bf16] @74880; Q[64x104] @148096;
//       SP[64x360] @161408 (fp16 S -> bf16 P in-place per row -> fp32 O stage).
#define AB_K  0
#define AB_V  74880
#define AB_Q  148096
#define AB_SP 161408
#define AT_SMEM 207488

__global__ __launch_bounds__(256, 1)
void k_attn(const __nv_bfloat16* __restrict__ Qh,
            const __nv_bfloat16* __restrict__ Kh,
            const __nv_bfloat16* __restrict__ Vh) {
    extern __shared__ char smb[];
    __nv_bfloat16* kh_s = (__nv_bfloat16*)(smb + AB_K);
    __nv_bfloat16* vh_s = (__nv_bfloat16*)(smb + AB_V);
    __nv_bfloat16* qh_s = (__nv_bfloat16*)(smb + AB_Q);
    __half*        s_h  = (__half*)(smb + AB_SP);         // S fp16, stride 360
    __nv_bfloat16* p_s  = (__nv_bfloat16*)(smb + AB_SP);  // P bf16, stride 360 (in place)
    float*         O_s  = (float*)(smb + AB_SP);          // O stage 96x66 fp32

    int win = blockIdx.x;
    int tid = threadIdx.x, lane = tid & 31, wp = tid >> 5;
    int g = lane >> 2, tg = lane & 3;
    int lr = lane & 15, lc = (lane & 16) ? 8 : 0;
    int wm = wp & 1, wn = wp >> 1;      // 2 x 4 warp grid

    const __nv_bfloat16* gqh = Qh + (size_t)win*WN*CDIM;
    const __nv_bfloat16* gkh = Kh + (size_t)win*WN*CDIM;
    const __nv_bfloat16* gvh = Vh + (size_t)win*WN*CDIM;
    float* ob = g_ot + (size_t)win*WN*CDIM;

    int ws = win >> 6, hs = (win >> 3) & 7, wd = win & 7;
    bool bz = (ws == 7), bh_ = (hs == 7), bw = (wd == 7);
    const float scale = 0.10206207261596575f;   // 1/sqrt(96)

    unsigned mzm = 0, mhm = 0, mwm = 0, mvm = 0;
    #pragma unroll
    for (int j = 0; j < 11; j++) {
        int m = lane + 32*j;
        if (m < WN) {
            int dzm = m / 49, rm = m % 49, dym = rm / 7, dxm = rm % 7;
            if (dzm < 4) mzm |= 1u << j;
            if (dym < 4) mhm |= 1u << j;
            if (dxm < 4) mwm |= 1u << j;
            mvm |= 1u << j;
        }
    }

    // ---- load K (343 rows; rows 343..359 stale, values masked) ----
    for (int e = tid; e < 343*24; e += 256) {
        int r = e / 24, c4 = e % 24;
        *(uint2*)(kh_s + r*104 + c4*4) = *(const uint2*)(gkh + (size_t)r*96 + c4*4);
    }
    // ---- load V (352 rows, zero pad 343..351) ----
    for (int e = tid; e < 352*24; e += 256) {
        int r = e / 24, c4 = e % 24;
        uint2 vv = make_uint2(0u, 0u);
        if (r < WN) vv = *(const uint2*)(gvh + (size_t)r*96 + c4*4);
        *(uint2*)(vh_s + r*104 + c4*4) = vv;
    }

    for (int chunk = 0; chunk < 6; chunk++) {
        int qbase = chunk * 64;
        // ---- stage Q chunk (zero pad rows) ----
        for (int e = tid; e < 64*24; e += 256) {
            int r = e / 24, c4 = e % 24;
            int q = qbase + r;
            uint2 vq = make_uint2(0u, 0u);
            if (q < WN) vq = *(const uint2*)(gqh + (size_t)q*96 + c4*4);
            *(uint2*)(qh_s + r*104 + c4*4) = vq;
        }
        __syncthreads();   // Q visible; K/V visible (1st); prev O reads done

        // ---- phase S: S[64x352] = Q Kt ----
        float sacc[2][11][4];
        #pragma unroll
        for (int rt = 0; rt < 2; rt++)
            #pragma unroll
            for (int ct = 0; ct < 11; ct++)
                #pragma unroll
                for (int i = 0; i < 4; i++) sacc[rt][ct][i] = 0.f;

        #pragma unroll
        for (int ks = 0; ks < 6; ks++) {
            int k0 = ks * 16;
            u32 aqh[2][4];
            #pragma unroll
            for (int rt = 0; rt < 2; rt++) {
                int ro = (wm*32 + rt*16 + lr)*104 + k0 + lc;
                ldmx4(aqh[rt], qh_s + ro);
            }
            #pragma unroll
            for (int bg = 0; bg < 6; bg++) {
                int n0 = wn*88 + bg*16;
                u32 bh[4];
                int ro = (n0 + lr)*104 + k0 + lc;
                ldmx4(bh, kh_s + ro);
                #pragma unroll
                for (int rt = 0; rt < 2; rt++) {
                    mma16816(sacc[rt][2*bg], aqh[rt], bh[0], bh[2]);
                    if (bg < 5)
                        mma16816(sacc[rt][2*bg+1], aqh[rt], bh[1], bh[3]);
                }
            }
        }

        // ---- store S fragments as fp16 (stride 360) ----
        #pragma unroll
        for (int rt = 0; rt < 2; rt++) {
            int row = wm*32 + rt*16 + g;
            #pragma unroll
            for (int ct = 0; ct < 11; ct++) {
                int col = wn*88 + ct*8 + 2*tg;
                *(__half2*)(s_h + row*360 + col)       = __floats2half2_rn(sacc[rt][ct][0], sacc[rt][ct][1]);
                *(__half2*)(s_h + (row + 8)*360 + col) = __floats2half2_rn(sacc[rt][ct][2], sacc[rt][ct][3]);
            }
        }
        __syncthreads();

        // ---- softmax: read fp16 S, write bf16 P in-place (same row) ----
        #pragma unroll
        for (int rr = 0; rr < 8; rr++) {
            int qr = wp*8 + rr;
            int q = qbase + qr;
            __nv_bfloat16* ph = p_s + qr*360;
            if (q < WN) {
                int dzq = q / 49, rq = q % 49, dyq = rq / 7, dxq = rq % 7;
                bool gz = dzq < 4, gh = dyq < 4, gw = dxq < 4;
                float sc[11];
                float mx = -1e30f;
                #pragma unroll
                for (int j = 0; j < 11; j++) {
                    float v;
                    if (mvm & (1u << j)) {
                        bool same = (!bz  || (gz == ((mzm >> j) & 1))) &&
                                    (!bh_ || (gh == ((mhm >> j) & 1))) &&
                                    (!bw  || (gw == ((mwm >> j) & 1)));
                        v = __half2float(s_h[qr*360 + lane + 32*j]) * scale + (same ? 0.f : -100.f);
                    } else v = -1e30f;
                    sc[j] = v;
                    mx = fmaxf(mx, v);
                }
                #pragma unroll
                for (int o = 16; o; o >>= 1) mx = fmaxf(mx, __shfl_xor_sync(0xffffffffu, mx, o));
                float ssum = 0.f;
                #pragma unroll
                for (int j = 0; j < 11; j++) { sc[j] = __expf(sc[j] - mx); ssum += sc[j]; }
                #pragma unroll
                for (int o = 16; o; o >>= 1) ssum += __shfl_xor_sync(0xffffffffu, ssum, o);
                float rinv = 1.f / ssum;
                __syncwarp();   // all S reads of this row done before overwrite
                #pragma unroll
                for (int j = 0; j < 11; j++) {
                    int m = lane + 32*j;
                    ph[m] = (mvm & (1u << j)) ? __float2bfloat16_rn(sc[j] * rinv)
                                              : __float2bfloat16(0.f);
                }
            } else {
                __nv_bfloat16 z = __float2bfloat16(0.f);
                __syncwarp();
                #pragma unroll
                for (int j = 0; j < 11; j++) ph[lane + 32*j] = z;
            }
            if (lane < 8) ph[352 + lane] = __float2bfloat16(0.f);
        }
        __syncthreads();

        // ---- phase PV: O[64x96] = P V (V resident, 22 k-tiles) ----
        float oacc[2][3][4];
        #pragma unroll
        for (int rt = 0; rt < 2; rt++)
            #pragma unroll
            for (int ct = 0; ct < 3; ct++)
                #pragma unroll
                for (int i = 0; i < 4; i++) oacc[rt][ct][i] = 0.f;

        #pragma unroll
        for (int s = 0; s < 22; s++) {
            int kg = s*16;
            u32 aph[2][4];
            #pragma unroll
            for (int rt = 0; rt < 2; rt++) {
                int ro = (wm*32 + rt*16 + lr)*360 + kg + lc;
                ldmx4(aph[rt], p_s + ro);
            }
            int n0 = wn*24;
            u32 bvh[6];
            {
                int ro = (kg + lr)*104 + n0 + lc;
                ldmx4t(bvh, vh_s + ro);
                int ro2 = (kg + lr)*104 + n0 + 16;
                ldmx2t(bvh + 4, vh_s + ro2);
            }
            #pragma unroll
            for (int rt = 0; rt < 2; rt++) {
                #pragma unroll
                for (int ct = 0; ct < 3; ct++)
                    mma16816(oacc[rt][ct], aph[rt], bvh[2*ct], bvh[2*ct+1]);
            }
        }
        __syncthreads();   // P reads done -> O stage may overwrite SP region

        #pragma unroll
        for (int rt = 0; rt < 2; rt++) {
            int row = wm*32 + rt*16 + g;
            #pragma unroll
            for (int ct = 0; ct < 3; ct++) {
                int col = wn*24 + ct*8 + 2*tg;
                O_s[(col)  *66 + row]     = oacc[rt][ct][0];
                O_s[(col+1)*66 + row]     = oacc[rt][ct][1];
                O_s[(col)  *66 + row + 8] = oacc[rt][ct][2];
                O_s[(col+1)*66 + row + 8] = oacc[rt][ct][3];
            }
        }
        __syncthreads();
        for (int e = tid; e < 96*64; e += 256) {
            int c = e >> 6, i = e & 63;
            int q = qbase + i;
            if (q < WN) ob[(size_t)c*WN + q] = O_s[c*66 + i];
        }
    }
}

// -------------------- window-reverse + roll(+3) + residual + LN2 --------------
__global__ __launch_bounds__(256)
void k_resln2(const float* __restrict__ x,
              const float* __restrict__ gg, const float* __restrict__ bb) {
    __shared__ float xs[32*101];
    int p0 = blockIdx.x * 32;
    int tid = threadIdx.x, lane = tid & 31, wp = tid >> 5;
    for (int e = tid; e < 96*32; e += 256) {
        int c = e >> 5, i = e & 31;
        xs[i*101 + c] = x[(size_t)c*NTOK + p0 + i];
    }
    __syncthreads();
    #pragma unroll
    for (int ii = wp; ii < 32; ii += 8) {
        int p = p0 + ii;
        int s = p / 3136, r = p % 3136, h = r / 56, w = r % 56;
        int s2 = (s >= 3) ? s - 3 : s + 53;
        int h2 = (h >= 3) ? h - 3 : h + 53;
        int w2 = (w >= 3) ? w - 3 : w + 53;
        int win = (s2/7)*64 + (h2/7)*8 + (w2/7);
        int np  = (s2%7)*49 + (h2%7)*7 + (w2%7);
        const float* ov = g_ot + (size_t)win*WN*CDIM + np*96;
        float v0 = xs[ii*101 + lane]      + ov[lane];
        float v1 = xs[ii*101 + lane + 32] + ov[lane + 32];
        float v2 = xs[ii*101 + lane + 64] + ov[lane + 64];
        float* xr = g_xres + (size_t)p*CDIM;
        xr[lane] = v0; xr[lane + 32] = v1; xr[lane + 64] = v2;
        float sum = v0 + v1 + v2, sq = v0*v0 + v1*v1 + v2*v2;
        #pragma unroll
        for (int o = 16; o; o >>= 1) {
            sum += __shfl_xor_sync(0xffffffffu, sum, o);
            sq  += __shfl_xor_sync(0xffffffffu, sq, o);
        }
        float mean = sum * (1.f/96.f);
        float var  = sq * (1.f/96.f) - mean*mean;
        float inv  = rsqrtf(var + 1e-5f);
        size_t yo = (size_t)p*CDIM;
        float y0 = (v0 - mean)*inv*gg[lane]      + bb[lane];
        float y1 = (v1 - mean)*inv*gg[lane + 32] + bb[lane + 32];
        float y2 = (v2 - mean)*inv*gg[lane + 64] + bb[lane + 64];
        bsplit(y0, g_l2h[yo + lane],      g_l2l[yo + lane]);
        bsplit(y1, g_l2h[yo + lane + 32], g_l2l[yo + lane + 32]);
        bsplit(y2, g_l2h[yo + lane + 64], g_l2l[yo + lane + 64]);
    }
}

// -------------------- launch ---------------------------------------------------
extern "C" void kernel_launch(void* const* d_in, const int* in_sizes, int n_in,
                              void* d_out, int out_size) {
    const float* x   = (const float*)d_in[0];
    const float* n1g = (const float*)d_in[1];
    const float* n1b = (const float*)d_in[2];
    const float* wq  = (const float*)d_in[3];
    const float* bq  = (const float*)d_in[4];
    const float* wk  = (const float*)d_in[5];
    const float* bk  = (const float*)d_in[6];
    const float* wv  = (const float*)d_in[7];
    const float* bv  = (const float*)d_in[8];
    const float* dqw = (const float*)d_in[9];
    const float* dqb = (const float*)d_in[10];
    const float* dkw = (const float*)d_in[11];
    const float* dkb = (const float*)d_in[12];
    const float* dvw = (const float*)d_in[13];
    const float* dvb = (const float*)d_in[14];
    const float* n2g = (const float*)d_in[15];
    const float* n2b = (const float*)d_in[16];
    const float* f1w = (const float*)d_in[17];
    const float* f1b = (const float*)d_in[18];
    const float* f2w = (const float*)d_in[19];
    const float* f2b = (const float*)d_in[20];
    float* out = (float*)d_out;

    float *pqp, *pkp, *pvp, *pxres, *pbqkv;
    __nv_bfloat16 *pxwh, *pl2h, *pl2l, *phh, *phl, *pwqh, *pf1h, *pf1l, *pf2h, *pf2l;
    __nv_bfloat16 *pqh, *pkh, *pvh;
    cudaGetSymbolAddress((void**)&pqp,  g_qp);
    cudaGetSymbolAddress((void**)&pkp,  g_kp);
    cudaGetSymbolAddress((void**)&pvp,  g_vp);
    cudaGetSymbolAddress((void**)&pxres,g_xres);
    cudaGetSymbolAddress((void**)&pbqkv,g_bqkv);
    cudaGetSymbolAddress((void**)&pxwh, g_xwh);
    cudaGetSymbolAddress((void**)&pl2h, g_l2h);
    cudaGetSymbolAddress((void**)&pl2l, g_l2l);
    cudaGetSymbolAddress((void**)&phh,  g_hh);
    cudaGetSymbolAddress((void**)&phl,  g_hl);
    cudaGetSymbolAddress((void**)&pwqh, g_wqh);
    cudaGetSymbolAddress((void**)&pf1h, g_f1h);
    cudaGetSymbolAddress((void**)&pf1l, g_f1l);
    cudaGetSymbolAddress((void**)&pf2h, g_f2h);
    cudaGetSymbolAddress((void**)&pf2l, g_f2l);
    cudaGetSymbolAddress((void**)&pqh,  g_qh);
    cudaGetSymbolAddress((void**)&pkh,  g_kh);
    cudaGetSymbolAddress((void**)&pvh,  g_vh);

    cudaFuncSetAttribute(k_attn, cudaFuncAttributeMaxDynamicSharedMemorySize, AT_SMEM);
    cudaFuncSetAttribute(k_tgemm<0>, cudaFuncAttributeMaxDynamicSharedMemorySize, TG_SMEM);
    cudaFuncSetAttribute(k_tgemm<1>, cudaFuncAttributeMaxDynamicSharedMemorySize, TG_SMEM);
    cudaFuncSetAttribute(k_tgemm<2>, cudaFuncAttributeMaxDynamicSharedMemorySize, TG_SMEM);

    k_prep1<<<(3*96*96 + 255)/256, 256>>>(wq, bq, wk, bk, wv, bv);
    k_prep2<<<(HIDD*96 + 255)/256, 256>>>(f1w, f2w);
    k_ln1<<<NTOK/64, 256>>>(x, n1g, n1b);

    // qkv: D = xw @ wqkv^T (+bias), single-pass bf16, 3 N-slices in-kernel
    k_tgemm<0><<<NTOK/128, 256, TG_SMEM>>>(pxwh, pxwh, pwqh, pwqh, pbqkv, 96,
                                           pqp, pkp, pvp, nullptr, nullptr, nullptr, nullptr);

    // depthwise -> single bf16 plane (fused q/k/v)
    dim3 gdw(NW, 3, 3);
    k_dw<<<gdw, 392>>>(pqp, pkp, pvp, dqw, dkw, dvw, dqb, dkb, dvb,
                       pqh, pkh, pvh);

    // tensor-core fused attention (K/V smem-resident)
    k_attn<<<NW, 256, AT_SMEM>>>(pqh, pkh, pvh);

    k_resln2<<<NTOK/32, 256>>>(x, n2g, n2b);

    // MLP1: GELU(ln2 @ f1w^T + f1b) -> bf16 hi/lo planes, 4 N-slices in-kernel
    k_tgemm<1><<<NTOK/128, 256, TG_SMEM>>>(pl2h, pl2l, pf1h, pf1l, f1b, 96,
                                           nullptr, nullptr, nullptr, phh, phl, nullptr, nullptr);
    // MLP2: out^T = (h @ f2w^T + f2b + xres)
    dim3 g3(NTOK/128, 1);
    k_tgemm<2><<<g3, 256, TG_SMEM>>>(phh, phl, pf2h, pf2l, f2b, HIDD,
                                     nullptr, nullptr, nullptr, nullptr, nullptr, pxres, out);
}